// round 11
// baseline (speedup 1.0000x reference)
#include <cuda_runtime.h>
#include <cuda_bf16.h>

// ---------------------------------------------------------------------------
// HiLo attention, b=8, dim=256, H=W=64, WS=2, 4+4 heads, head_dim=32
// Round 11: R9 base (tcgen05 unavailable: harness compiles -arch=sm_100).
// Change: pass-major HMMA issue order (break per-accumulator RAW chains)
// in both GEMMs and lofi attention. Math order per accumulator unchanged.
// ---------------------------------------------------------------------------

#define BB 8
#define CDIM 256
#define NTOK 4096          // 64*64 tokens per batch
#define MPOOL 1024         // 32*32 pooled tokens per batch
#define ATTN_SCALE 0.17677669529663687f   // 32^-0.5

typedef unsigned long long u64;
typedef unsigned int u32;

// fp32 intermediates (attention inputs)
__device__ float g_qkv [BB * NTOK * 384];   // hifi qkv  [b][t][s*128+head*32+d]
__device__ float g_ql  [BB * NTOK * 128];   // lofi q    [b][t][head*32+d]
__device__ float g_kvl [BB * MPOOL * 256];  // lofi kv   [b][m][s*128+head*32+d]

// bf16 hi/lo operand tensors
__device__ __nv_bfloat16 g_xhi [BB * CDIM * NTOK];   // x       [b][c][t] K-major
__device__ __nv_bfloat16 g_xlo [BB * CDIM * NTOK];
__device__ __nv_bfloat16 g_phi [BB * CDIM * MPOOL];  // pooled  [b][c][m] K-major
__device__ __nv_bfloat16 g_plo [BB * CDIM * MPOOL];
__device__ __nv_bfloat16 g_whi [229376];             // all weights, see offsets
__device__ __nv_bfloat16 g_wlo [229376];
__device__ __nv_bfloat16 g_ohhi[BB * NTOK * 128];    // hifi attn out [b][t][c]
__device__ __nv_bfloat16 g_ohlo[BB * NTOK * 128];
__device__ __nv_bfloat16 g_olhi[BB * NTOK * 128];    // lofi attn out
__device__ __nv_bfloat16 g_ollo[BB * NTOK * 128];

// weight segment offsets in g_whi/g_wlo
#define WOFF_HQKV   0        // 256*384
#define WOFF_LQ     98304    // 256*128
#define WOFF_LKV    131072   // 256*256
#define WOFF_HPROJ  196608   // 128*128
#define WOFF_LPROJ  212992   // 128*128

// ---- helpers ---------------------------------------------------------------
__device__ __forceinline__ void mma_bf16(
    float* c, const u32* a, u32 b0, u32 b1)
{
    asm volatile(
        "mma.sync.aligned.m16n8k16.row.col.f32.bf16.bf16.f32 "
        "{%0,%1,%2,%3}, {%4,%5,%6,%7}, {%8,%9}, {%0,%1,%2,%3};\n"
        : "+f"(c[0]), "+f"(c[1]), "+f"(c[2]), "+f"(c[3])
        : "r"(a[0]), "r"(a[1]), "r"(a[2]), "r"(a[3]), "r"(b0), "r"(b1));
}
// split two floats into packed bf16x2 hi + residual bf16x2 lo (mem order x0,x1)
__device__ __forceinline__ void bf16_split2(float x0, float x1, u32& hi, u32& lo)
{
    asm("cvt.rn.bf16x2.f32 %0, %1, %2;" : "=r"(hi) : "f"(x1), "f"(x0));
    float h0 = __uint_as_float(hi << 16);
    float h1 = __uint_as_float(hi & 0xffff0000u);
    asm("cvt.rn.bf16x2.f32 %0, %1, %2;" : "=r"(lo) : "f"(x1 - h1), "f"(x0 - h0));
}
__device__ __forceinline__ u32 s2u(const void* p) {
    return (u32)__cvta_generic_to_shared(p);
}
__device__ __forceinline__ void ldsm_x4_t(u32& r0, u32& r1, u32& r2, u32& r3, u32 addr)
{
    asm volatile("ldmatrix.sync.aligned.m8n8.x4.trans.shared.b16 "
                 "{%0,%1,%2,%3}, [%4];"
                 : "=r"(r0), "=r"(r1), "=r"(r2), "=r"(r3) : "r"(addr));
}
__device__ __forceinline__ void ldsm_x4(u32& r0, u32& r1, u32& r2, u32& r3, u32 addr)
{
    asm volatile("ldmatrix.sync.aligned.m8n8.x4.shared.b16 "
                 "{%0,%1,%2,%3}, [%4];"
                 : "=r"(r0), "=r"(r1), "=r"(r2), "=r"(r3) : "r"(addr));
}
__device__ __forceinline__ void cp_cg(u32 dst, const void* src)
{
    asm volatile("cp.async.cg.shared.global [%0], [%1], 16;\n"
                 :: "r"(dst), "l"(src));
}
#define CP_COMMIT() asm volatile("cp.async.commit_group;\n")

// ---------------------------------------------------------------------------
// convert x -> bf16 hi/lo and fused 2x2 avg pool -> bf16 hi/lo
// ---------------------------------------------------------------------------
__global__ __launch_bounds__(256) void convert_x_pool(const float* __restrict__ x)
{
    const int bc = blockIdx.x;
    const float* xp = x + (long)bc * 4096;
    __nv_bfloat16* xh = g_xhi + (long)bc * 4096;
    __nv_bfloat16* xl = g_xlo + (long)bc * 4096;
#pragma unroll
    for (int p = 0; p < 4; p++) {
        const int i = threadIdx.x * 4 + p * 1024;
        float4 v = *(const float4*)&xp[i];
        u32 h01, l01, h23, l23;
        bf16_split2(v.x, v.y, h01, l01);
        bf16_split2(v.z, v.w, h23, l23);
        *(u32*)&xh[i] = h01; *(u32*)&xh[i + 2] = h23;
        *(u32*)&xl[i] = l01; *(u32*)&xl[i + 2] = l23;
    }
    __nv_bfloat16* ph = g_phi + (long)bc * 1024;
    __nv_bfloat16* pl = g_plo + (long)bc * 1024;
#pragma unroll
    for (int p = 0; p < 2; p++) {
        const int m = threadIdx.x * 2 + p * 512;
        const int hg = m >> 5, wg = m & 31;
        const float* r0 = xp + hg * 128 + wg * 2;
        float4 a = *(const float4*)&r0[0];
        float4 b = *(const float4*)&r0[64];
        float p0 = 0.25f * (a.x + a.y + b.x + b.y);
        float p1 = 0.25f * (a.z + a.w + b.z + b.w);
        u32 h, l;
        bf16_split2(p0, p1, h, l);
        *(u32*)&ph[m] = h;
        *(u32*)&pl[m] = l;
    }
}

// ---------------------------------------------------------------------------
// convert all 5 weight matrices into g_whi/g_wlo (229376 elems)
// ---------------------------------------------------------------------------
__global__ __launch_bounds__(256) void convert_w(
    const float* __restrict__ w0, const float* __restrict__ w1,
    const float* __restrict__ w2, const float* __restrict__ w3,
    const float* __restrict__ w4)
{
    const long idx = ((long)blockIdx.x * 256 + threadIdx.x) * 4;
    const float* src; long off;
    if (idx < WOFF_LQ)         { src = w0; off = 0; }
    else if (idx < WOFF_LKV)   { src = w1; off = WOFF_LQ; }
    else if (idx < WOFF_HPROJ) { src = w2; off = WOFF_LKV; }
    else if (idx < WOFF_LPROJ) { src = w3; off = WOFF_HPROJ; }
    else                       { src = w4; off = WOFF_LPROJ; }
    float4 v = *(const float4*)&src[idx - off];
    u32 h01, l01, h23, l23;
    bf16_split2(v.x, v.y, h01, l01);
    bf16_split2(v.z, v.w, h23, l23);
    *(u32*)&g_whi[idx] = h01; *(u32*)&g_whi[idx + 2] = h23;
    *(u32*)&g_wlo[idx] = l01; *(u32*)&g_wlo[idx + 2] = l23;
}

// ---------------------------------------------------------------------------
// 3-stage pipelined bf16x3 GEMM, A K-major bf16 hi/lo.
// K=256, BM=128, BN=64, BK=32, 256 thr (8 warps 4m x 2n).
// Smem: 3 stages x (A 2x32x136 + W 2x32x72) bf16 = 79872 B.
// Pass-major HMMA issue (8 independent accumulators between RAW reuses).
// ---------------------------------------------------------------------------
#define XT_SMEM 79872
__global__ __launch_bounds__(256, 2) void gemm_xt_pipe(
    const __nv_bfloat16* __restrict__ Ahi, const __nv_bfloat16* __restrict__ Alo,
    long aBatch, int woff,
    float* __restrict__ Cout, long cBatch, int M, int N)
{
    extern __shared__ char smraw[];
    const u32 sbase = s2u(smraw);
#define SA_(st,hl,k,m) (sbase + (((((st)*2+(hl))*32)+(k))*136 + (m))*2)
#define SW_(st,hl,k,n) (sbase + 52224 + (((((st)*2+(hl))*32)+(k))*72 + (n))*2)

    const int tid = threadIdx.x;
    const int wid = tid >> 5;
    const int lane = tid & 31;
    const int m0 = blockIdx.x * 128;
    const int n0 = blockIdx.y * 64;
    const int wm = (wid & 3) * 32;
    const int wn = (wid >> 2) * 32;
    const __nv_bfloat16* Ah = Ahi + (long)blockIdx.z * aBatch + m0;
    const __nv_bfloat16* Al = Alo + (long)blockIdx.z * aBatch + m0;
    const __nv_bfloat16* Wh = g_whi + woff + n0;
    const __nv_bfloat16* Wl = g_wlo + woff + n0;
    float* Cb = Cout + (long)blockIdx.z * cBatch;

    const int l7 = lane & 7;
    const int a_koff = l7 + ((lane & 16) ? 8 : 0);
    const int a_moff = (lane & 8) ? 8 : 0;
    const int b_koff = l7 + ((lane & 8) ? 8 : 0);
    const int b_noff = (lane & 16) ? 8 : 0;

    const int ar0 = tid >> 4,          ac0 = (tid & 15) * 8;
    const int ar1 = (tid + 256) >> 4,  ac1 = ((tid + 256) & 15) * 8;
    const int wr = tid >> 3,           wc = (tid & 7) * 8;

    auto issue_chunk = [&](int st, int chunk) {
        const long kb = (long)chunk * 32;
        cp_cg(SA_(st, 0, ar0, ac0), Ah + (kb + ar0) * M + ac0);
        cp_cg(SA_(st, 1, ar0, ac0), Al + (kb + ar0) * M + ac0);
        cp_cg(SA_(st, 0, ar1, ac1), Ah + (kb + ar1) * M + ac1);
        cp_cg(SA_(st, 1, ar1, ac1), Al + (kb + ar1) * M + ac1);
        cp_cg(SW_(st, 0, wr, wc), Wh + (kb + wr) * N + wc);
        cp_cg(SW_(st, 1, wr, wc), Wl + (kb + wr) * N + wc);
        CP_COMMIT();
    };

    float acc[2][4][4];
#pragma unroll
    for (int i = 0; i < 2; i++)
#pragma unroll
        for (int j = 0; j < 4; j++)
#pragma unroll
            for (int c = 0; c < 4; c++) acc[i][j][c] = 0.f;

    issue_chunk(0, 0);
    issue_chunk(1, 1);

#pragma unroll
    for (int it = 0; it < 8; it++) {
        if (it < 7) asm volatile("cp.async.wait_group 1;\n");
        else        asm volatile("cp.async.wait_group 0;\n");
        __syncthreads();
        if (it + 2 < 8) issue_chunk((it + 2) % 3, it + 2);

        const int st = it % 3;
#pragma unroll
        for (int ks = 0; ks < 2; ks++) {
            const int kk = ks * 16;
            u32 ahi[2][4], alo[2][4];
#pragma unroll
            for (int i = 0; i < 2; i++) {
                const int mb = wm + i * 16;
                ldsm_x4_t(ahi[i][0], ahi[i][1], ahi[i][2], ahi[i][3],
                          SA_(st, 0, kk + a_koff, mb + a_moff));
                ldsm_x4_t(alo[i][0], alo[i][1], alo[i][2], alo[i][3],
                          SA_(st, 1, kk + a_koff, mb + a_moff));
            }
            u32 bhi[4][2], blo[4][2];
#pragma unroll
            for (int np = 0; np < 2; np++) {
                const int nb2 = wn + np * 16;
                u32 r0, r1, r2, r3;
                ldsm_x4_t(r0, r1, r2, r3, SW_(st, 0, kk + b_koff, nb2 + b_noff));
                bhi[2 * np][0] = r0; bhi[2 * np][1] = r1;
                bhi[2 * np + 1][0] = r2; bhi[2 * np + 1][1] = r3;
                ldsm_x4_t(r0, r1, r2, r3, SW_(st, 1, kk + b_koff, nb2 + b_noff));
                blo[2 * np][0] = r0; blo[2 * np][1] = r1;
                blo[2 * np + 1][0] = r2; blo[2 * np + 1][1] = r3;
            }
            // pass-major: all 8 accumulators between reuses of the same acc
#pragma unroll
            for (int i = 0; i < 2; i++)
#pragma unroll
                for (int j = 0; j < 4; j++)
                    mma_bf16(acc[i][j], ahi[i], bhi[j][0], bhi[j][1]);
#pragma unroll
            for (int i = 0; i < 2; i++)
#pragma unroll
                for (int j = 0; j < 4; j++)
                    mma_bf16(acc[i][j], alo[i], bhi[j][0], bhi[j][1]);
#pragma unroll
            for (int i = 0; i < 2; i++)
#pragma unroll
                for (int j = 0; j < 4; j++)
                    mma_bf16(acc[i][j], ahi[i], blo[j][0], blo[j][1]);
        }
    }

    const int g = lane >> 2, tg = lane & 3;
#pragma unroll
    for (int i = 0; i < 2; i++)
#pragma unroll
        for (int j = 0; j < 4; j++) {
            const int row = m0 + wm + i * 16 + g;
            const int col = n0 + wn + j * 8 + 2 * tg;
            *(float2*)&Cb[(long)row * N + col] =
                make_float2(acc[i][j][0], acc[i][j][1]);
            *(float2*)&Cb[(long)(row + 8) * N + col] =
                make_float2(acc[i][j][2], acc[i][j][3]);
        }
#undef SA_
#undef SW_
}

// ---------------------------------------------------------------------------
// 3-stage pipelined bf16x3 projection GEMM, K=128, A row-major [M][128].
// out[(b*256+coff+n)*4096+m] = bias[n] + A@W. Pass-major HMMA issue.
// Smem: 3 x (A 2x128x40 + W 2x32x72) bf16 = 89088 B.
// ---------------------------------------------------------------------------
#define PJ_SMEM 89088
__global__ __launch_bounds__(256, 2) void gemm_proj_pipe(
    const __nv_bfloat16* __restrict__ Ahi, const __nv_bfloat16* __restrict__ Alo,
    long aBatch, int woff,
    const float* __restrict__ bias,
    float* __restrict__ out, int coff)
{
    extern __shared__ char smraw[];
    const u32 sbase = s2u(smraw);
#define SA_(st,hl,m,k) (sbase + (((((st)*2+(hl))*128)+(m))*40 + (k))*2)
#define SW_(st,hl,k,n) (sbase + 61440 + (((((st)*2+(hl))*32)+(k))*72 + (n))*2)

    const int tid = threadIdx.x;
    const int wid = tid >> 5;
    const int lane = tid & 31;
    const int m0 = blockIdx.x * 128;
    const int n0 = blockIdx.y * 64;
    const int wm = (wid & 3) * 32;
    const int wn = (wid >> 2) * 32;
    const __nv_bfloat16* Ah = Ahi + (long)blockIdx.z * aBatch + (long)m0 * 128;
    const __nv_bfloat16* Al = Alo + (long)blockIdx.z * aBatch + (long)m0 * 128;
    const __nv_bfloat16* Wh = g_whi + woff + n0;
    const __nv_bfloat16* Wl = g_wlo + woff + n0;

    const int l7 = lane & 7;
    const int a_moff = l7 + ((lane & 8) ? 8 : 0);
    const int a_koff = (lane & 16) ? 8 : 0;
    const int b_koff = l7 + ((lane & 8) ? 8 : 0);
    const int b_noff = (lane & 16) ? 8 : 0;

    const int ar0 = tid >> 2,          ac0 = (tid & 3) * 8;
    const int ar1 = (tid + 256) >> 2,  ac1 = ((tid + 256) & 3) * 8;
    const int wr = tid >> 3,           wc = (tid & 7) * 8;

    auto issue_chunk = [&](int st, int chunk) {
        const long kb = (long)chunk * 32;
        cp_cg(SA_(st, 0, ar0, ac0), Ah + (long)ar0 * 128 + kb + ac0);
        cp_cg(SA_(st, 1, ar0, ac0), Al + (long)ar0 * 128 + kb + ac0);
        cp_cg(SA_(st, 0, ar1, ac1), Ah + (long)ar1 * 128 + kb + ac1);
        cp_cg(SA_(st, 1, ar1, ac1), Al + (long)ar1 * 128 + kb + ac1);
        cp_cg(SW_(st, 0, wr, wc), Wh + (kb + wr) * 128 + wc);
        cp_cg(SW_(st, 1, wr, wc), Wl + (kb + wr) * 128 + wc);
        CP_COMMIT();
    };

    float acc[2][4][4];
#pragma unroll
    for (int i = 0; i < 2; i++)
#pragma unroll
        for (int j = 0; j < 4; j++)
#pragma unroll
            for (int c = 0; c < 4; c++) acc[i][j][c] = 0.f;

    issue_chunk(0, 0);
    issue_chunk(1, 1);

#pragma unroll
    for (int it = 0; it < 4; it++) {
        if (it < 3) asm volatile("cp.async.wait_group 1;\n");
        else        asm volatile("cp.async.wait_group 0;\n");
        __syncthreads();
        if (it + 2 < 4) issue_chunk((it + 2) % 3, it + 2);

        const int st = it % 3;
#pragma unroll
        for (int ks = 0; ks < 2; ks++) {
            const int kk = ks * 16;
            u32 ahi[2][4], alo[2][4];
#pragma unroll
            for (int i = 0; i < 2; i++) {
                const int mb = wm + i * 16;
                ldsm_x4(ahi[i][0], ahi[i][1], ahi[i][2], ahi[i][3],
                        SA_(st, 0, mb + a_moff, kk + a_koff));
                ldsm_x4(alo[i][0], alo[i][1], alo[i][2], alo[i][3],
                        SA_(st, 1, mb + a_moff, kk + a_koff));
            }
            u32 bhi[4][2], blo[4][2];
#pragma unroll
            for (int np = 0; np < 2; np++) {
                const int nb2 = wn + np * 16;
                u32 r0, r1, r2, r3;
                ldsm_x4_t(r0, r1, r2, r3, SW_(st, 0, kk + b_koff, nb2 + b_noff));
                bhi[2 * np][0] = r0; bhi[2 * np][1] = r1;
                bhi[2 * np + 1][0] = r2; bhi[2 * np + 1][1] = r3;
                ldsm_x4_t(r0, r1, r2, r3, SW_(st, 1, kk + b_koff, nb2 + b_noff));
                blo[2 * np][0] = r0; blo[2 * np][1] = r1;
                blo[2 * np + 1][0] = r2; blo[2 * np + 1][1] = r3;
            }
            // pass-major HMMA issue
#pragma unroll
            for (int i = 0; i < 2; i++)
#pragma unroll
                for (int j = 0; j < 4; j++)
                    mma_bf16(acc[i][j], ahi[i], bhi[j][0], bhi[j][1]);
#pragma unroll
            for (int i = 0; i < 2; i++)
#pragma unroll
                for (int j = 0; j < 4; j++)
                    mma_bf16(acc[i][j], alo[i], bhi[j][0], bhi[j][1]);
#pragma unroll
            for (int i = 0; i < 2; i++)
#pragma unroll
                for (int j = 0; j < 4; j++)
                    mma_bf16(acc[i][j], ahi[i], blo[j][0], blo[j][1]);
        }
    }

    const int g = lane >> 2, tg = lane & 3;
    float* ob = out + ((long)blockIdx.z * 256 + coff) * 4096;
#pragma unroll
    for (int j = 0; j < 4; j++) {
        const int nl = n0 + wn + j * 8 + 2 * tg;
        const float bv0 = bias[nl];
        const float bv1 = bias[nl + 1];
#pragma unroll
        for (int i = 0; i < 2; i++) {
            const int m = m0 + wm + i * 16 + g;
            ob[(long)nl * 4096 + m]           = acc[i][j][0] + bv0;
            ob[(long)(nl + 1) * 4096 + m]     = acc[i][j][1] + bv1;
            ob[(long)nl * 4096 + m + 8]       = acc[i][j][2] + bv0;
            ob[(long)(nl + 1) * 4096 + m + 8] = acc[i][j][3] + bv1;
        }
    }
#undef SA_
#undef SW_
}

// ---------------------------------------------------------------------------
// hifi window attention: one warp per (b, window, head); emits bf16 hi/lo.
// ---------------------------------------------------------------------------
__global__ __launch_bounds__(256) void hifi_attn()
{
    const int wid = (blockIdx.x * blockDim.x + threadIdx.x) >> 5;
    const int lane = threadIdx.x & 31;
    const int head = wid & 3;
    const int win = (wid >> 2) & 1023;
    const int b = wid >> 12;
    const int hg = win >> 5, wgc = win & 31;

    float q[4], k[4], v[4];
    int t[4];
#pragma unroll
    for (int i = 0; i < 4; i++) {
        const int r = 2 * hg + (i >> 1);
        const int c = 2 * wgc + (i & 1);
        t[i] = r * 64 + c;
        const float* base = g_qkv + (long)(b * NTOK + t[i]) * 384 + head * 32 + lane;
        q[i] = base[0];
        k[i] = base[128];
        v[i] = base[256];
    }
    float s[4][4];
#pragma unroll
    for (int i = 0; i < 4; i++)
#pragma unroll
        for (int j = 0; j < 4; j++) {
            float p = q[i] * k[j];
#pragma unroll
            for (int off = 16; off; off >>= 1)
                p += __shfl_xor_sync(0xffffffffu, p, off);
            s[i][j] = p * ATTN_SCALE;
        }
#pragma unroll
    for (int i = 0; i < 4; i++) {
        float mx = fmaxf(fmaxf(s[i][0], s[i][1]), fmaxf(s[i][2], s[i][3]));
        float e0 = __expf(s[i][0] - mx);
        float e1 = __expf(s[i][1] - mx);
        float e2 = __expf(s[i][2] - mx);
        float e3 = __expf(s[i][3] - mx);
        float inv = 1.0f / (e0 + e1 + e2 + e3);
        float o = (e0 * v[0] + e1 * v[1] + e2 * v[2] + e3 * v[3]) * inv;
        const long idx = (long)(b * NTOK + t[i]) * 128 + head * 32 + lane;
        __nv_bfloat16 h = __float2bfloat16(o);
        g_ohhi[idx] = h;
        g_ohlo[idx] = __float2bfloat16(o - __bfloat162float(h));
    }
}

// ---------------------------------------------------------------------------
// lofi flash attention on tensor cores (bf16x3, m16n8k16); emits bf16 hi/lo.
// Pass-major HMMA issue in QK (groups of 4 score tiles) and PV (4 d-tiles).
// ---------------------------------------------------------------------------
__global__ __launch_bounds__(256, 2) void lofi_attn_mma()
{
    __shared__ __nv_bfloat16 sKhi[64][40];
    __shared__ __nv_bfloat16 sKlo[64][40];
    __shared__ __nv_bfloat16 sVhi[32][72];
    __shared__ __nv_bfloat16 sVlo[32][72];

    const int tid = threadIdx.x;
    const int lane = tid & 31;
    const int warp = tid >> 5;
    const int g = lane >> 2;
    const int tg = lane & 3;
    const int bh = blockIdx.y;
    const int b = bh >> 2, head = bh & 3;
    const int qrow0 = blockIdx.x * 128 + warp * 16;

    const float* qbase = g_ql + ((long)(b * NTOK + qrow0)) * 128 + head * 32;
    u32 qa_hi[2][4], qa_lo[2][4];
#pragma unroll
    for (int kt = 0; kt < 2; kt++) {
        float2 f0 = *(const float2*)&qbase[(long)g * 128 + kt * 16 + 2 * tg];
        float2 f1 = *(const float2*)&qbase[(long)(g + 8) * 128 + kt * 16 + 2 * tg];
        float2 f2 = *(const float2*)&qbase[(long)g * 128 + kt * 16 + 8 + 2 * tg];
        float2 f3 = *(const float2*)&qbase[(long)(g + 8) * 128 + kt * 16 + 8 + 2 * tg];
        bf16_split2(f0.x * ATTN_SCALE, f0.y * ATTN_SCALE, qa_hi[kt][0], qa_lo[kt][0]);
        bf16_split2(f1.x * ATTN_SCALE, f1.y * ATTN_SCALE, qa_hi[kt][1], qa_lo[kt][1]);
        bf16_split2(f2.x * ATTN_SCALE, f2.y * ATTN_SCALE, qa_hi[kt][2], qa_lo[kt][2]);
        bf16_split2(f3.x * ATTN_SCALE, f3.y * ATTN_SCALE, qa_hi[kt][3], qa_lo[kt][3]);
    }

    float od[4][4];
#pragma unroll
    for (int dt = 0; dt < 4; dt++)
#pragma unroll
        for (int c = 0; c < 4; c++) od[dt][c] = 0.f;
    float mrow[2] = {-1e30f, -1e30f};
    float lrow[2] = {0.f, 0.f};

    const float* kvb = g_kvl + (long)b * MPOOL * 256 + head * 32;

    for (int j0 = 0; j0 < MPOOL; j0 += 64) {
        __syncthreads();
#pragma unroll
        for (int p = 0; p < 2; p++) {
            const int idx = tid + 256 * p;
            const int r = idx >> 3;
            const int c4 = (idx & 7) * 4;
            const float* row = &kvb[(long)(j0 + r) * 256];
            float4 kf = *(const float4*)&row[c4];
            u32 h0, l0, h1, l1;
            bf16_split2(kf.x, kf.y, h0, l0);
            bf16_split2(kf.z, kf.w, h1, l1);
            *(u32*)&sKhi[r][c4]     = h0;
            *(u32*)&sKhi[r][c4 + 2] = h1;
            *(u32*)&sKlo[r][c4]     = l0;
            *(u32*)&sKlo[r][c4 + 2] = l1;
            float4 vf = *(const float4*)&row[128 + c4];
#pragma unroll
            for (int i = 0; i < 4; i++) {
                float v = (&vf.x)[i];
                __nv_bfloat16 vh = __float2bfloat16(v);
                sVhi[c4 + i][r] = vh;
                sVlo[c4 + i][r] = __float2bfloat16(v - __bfloat162float(vh));
            }
        }
        __syncthreads();

        // --- QK^T, pass-major in groups of 4 score tiles ---
        float s[8][4];
#pragma unroll
        for (int nt = 0; nt < 8; nt++)
#pragma unroll
            for (int c = 0; c < 4; c++) s[nt][c] = 0.f;
#pragma unroll
        for (int kt = 0; kt < 2; kt++) {
            const int kk = kt * 16;
#pragma unroll
            for (int g4 = 0; g4 < 8; g4 += 4) {
                u32 kbh[4][2], kbl[4][2];
#pragma unroll
                for (int q = 0; q < 4; q++) {
                    const int kv = (g4 + q) * 8 + g;
                    kbh[q][0] = *(const u32*)&sKhi[kv][kk + 2 * tg];
                    kbh[q][1] = *(const u32*)&sKhi[kv][kk + 8 + 2 * tg];
                    kbl[q][0] = *(const u32*)&sKlo[kv][kk + 2 * tg];
                    kbl[q][1] = *(const u32*)&sKlo[kv][kk + 8 + 2 * tg];
                }
#pragma unroll
                for (int q = 0; q < 4; q++)
                    mma_bf16(s[g4 + q], qa_hi[kt], kbh[q][0], kbh[q][1]);
#pragma unroll
                for (int q = 0; q < 4; q++)
                    mma_bf16(s[g4 + q], qa_lo[kt], kbh[q][0], kbh[q][1]);
#pragma unroll
                for (int q = 0; q < 4; q++)
                    mma_bf16(s[g4 + q], qa_hi[kt], kbl[q][0], kbl[q][1]);
            }
        }

        float mx0 = s[0][0], mx1 = s[0][2];
#pragma unroll
        for (int nt = 0; nt < 8; nt++) {
            mx0 = fmaxf(mx0, fmaxf(s[nt][0], s[nt][1]));
            mx1 = fmaxf(mx1, fmaxf(s[nt][2], s[nt][3]));
        }
        mx0 = fmaxf(mx0, __shfl_xor_sync(0xffffffffu, mx0, 1));
        mx0 = fmaxf(mx0, __shfl_xor_sync(0xffffffffu, mx0, 2));
        mx1 = fmaxf(mx1, __shfl_xor_sync(0xffffffffu, mx1, 1));
        mx1 = fmaxf(mx1, __shfl_xor_sync(0xffffffffu, mx1, 2));

        const float mn0 = fmaxf(mrow[0], mx0);
        const float mn1 = fmaxf(mrow[1], mx1);
        const float sf0 = __expf(mrow[0] - mn0);
        const float sf1 = __expf(mrow[1] - mn1);
        mrow[0] = mn0; mrow[1] = mn1;
        lrow[0] *= sf0; lrow[1] *= sf1;
#pragma unroll
        for (int dt = 0; dt < 4; dt++) {
            od[dt][0] *= sf0; od[dt][1] *= sf0;
            od[dt][2] *= sf1; od[dt][3] *= sf1;
        }
#pragma unroll
        for (int nt = 0; nt < 8; nt++) {
            s[nt][0] = __expf(s[nt][0] - mn0);
            s[nt][1] = __expf(s[nt][1] - mn0);
            s[nt][2] = __expf(s[nt][2] - mn1);
            s[nt][3] = __expf(s[nt][3] - mn1);
            lrow[0] += s[nt][0] + s[nt][1];
            lrow[1] += s[nt][2] + s[nt][3];
        }

        // --- PV, pass-major across 4 d-tiles ---
#pragma unroll
        for (int kt2 = 0; kt2 < 4; kt2++) {
            u32 pa_hi[4], pa_lo[4];
            bf16_split2(s[2 * kt2][0],     s[2 * kt2][1],     pa_hi[0], pa_lo[0]);
            bf16_split2(s[2 * kt2][2],     s[2 * kt2][3],     pa_hi[1], pa_lo[1]);
            bf16_split2(s[2 * kt2 + 1][0], s[2 * kt2 + 1][1], pa_hi[2], pa_lo[2]);
            bf16_split2(s[2 * kt2 + 1][2], s[2 * kt2 + 1][3], pa_hi[3], pa_lo[3]);
            const int kv0 = kt2 * 16;
            u32 vbh[4][2], vbl[4][2];
#pragma unroll
            for (int dt = 0; dt < 4; dt++) {
                const int d = dt * 8 + g;
                vbh[dt][0] = *(const u32*)&sVhi[d][kv0 + 2 * tg];
                vbh[dt][1] = *(const u32*)&sVhi[d][kv0 + 8 + 2 * tg];
                vbl[dt][0] = *(const u32*)&sVlo[d][kv0 + 2 * tg];
                vbl[dt][1] = *(const u32*)&sVlo[d][kv0 + 8 + 2 * tg];
            }
#pragma unroll
            for (int dt = 0; dt < 4; dt++)
                mma_bf16(od[dt], pa_hi, vbh[dt][0], vbh[dt][1]);
#pragma unroll
            for (int dt = 0; dt < 4; dt++)
                mma_bf16(od[dt], pa_lo, vbh[dt][0], vbh[dt][1]);
#pragma unroll
            for (int dt = 0; dt < 4; dt++)
                mma_bf16(od[dt], pa_hi, vbl[dt][0], vbl[dt][1]);
        }
    }

    lrow[0] += __shfl_xor_sync(0xffffffffu, lrow[0], 1);
    lrow[0] += __shfl_xor_sync(0xffffffffu, lrow[0], 2);
    lrow[1] += __shfl_xor_sync(0xffffffffu, lrow[1], 1);
    lrow[1] += __shfl_xor_sync(0xffffffffu, lrow[1], 2);
    const float inv0 = 1.0f / lrow[0];
    const float inv1 = 1.0f / lrow[1];

    const long obase = ((long)(b * NTOK + qrow0)) * 128 + head * 32;
#pragma unroll
    for (int dt = 0; dt < 4; dt++) {
        const int col = dt * 8 + 2 * tg;
        u32 h, l;
        bf16_split2(od[dt][0] * inv0, od[dt][1] * inv0, h, l);
        *(u32*)&g_olhi[obase + (long)g * 128 + col] = h;
        *(u32*)&g_ollo[obase + (long)g * 128 + col] = l;
        bf16_split2(od[dt][2] * inv1, od[dt][3] * inv1, h, l);
        *(u32*)&g_olhi[obase + (long)(g + 8) * 128 + col] = h;
        *(u32*)&g_ollo[obase + (long)(g + 8) * 128 + col] = l;
    }
}

// ---------------------------------------------------------------------------
extern "C" void kernel_launch(void* const* d_in, const int* in_sizes, int n_in,
                              void* d_out, int out_size)
{
    const float* x        = (const float*)d_in[0];
    const float* l_q_w    = (const float*)d_in[1];
    const float* l_kv_w   = (const float*)d_in[2];
    const float* l_proj_w = (const float*)d_in[3];
    const float* l_proj_b = (const float*)d_in[4];
    const float* h_qkv_w  = (const float*)d_in[5];
    const float* h_proj_w = (const float*)d_in[6];
    const float* h_proj_b = (const float*)d_in[7];
    float* out = (float*)d_out;

    cudaFuncSetAttribute(gemm_xt_pipe,
                         cudaFuncAttributeMaxDynamicSharedMemorySize, XT_SMEM);
    cudaFuncSetAttribute(gemm_proj_pipe,
                         cudaFuncAttributeMaxDynamicSharedMemorySize, PJ_SMEM);

    float *qkv, *ql, *kvl;
    __nv_bfloat16 *xhi, *xlo, *phi, *plo, *ohhi, *ohlo, *olhi, *ollo;
    cudaGetSymbolAddress((void**)&qkv,  g_qkv);
    cudaGetSymbolAddress((void**)&ql,   g_ql);
    cudaGetSymbolAddress((void**)&kvl,  g_kvl);
    cudaGetSymbolAddress((void**)&xhi,  g_xhi);
    cudaGetSymbolAddress((void**)&xlo,  g_xlo);
    cudaGetSymbolAddress((void**)&phi,  g_phi);
    cudaGetSymbolAddress((void**)&plo,  g_plo);
    cudaGetSymbolAddress((void**)&ohhi, g_ohhi);
    cudaGetSymbolAddress((void**)&ohlo, g_ohlo);
    cudaGetSymbolAddress((void**)&olhi, g_olhi);
    cudaGetSymbolAddress((void**)&ollo, g_ollo);

    // operand conversion
    convert_w<<<224, 256>>>(h_qkv_w, l_q_w, l_kv_w, h_proj_w, l_proj_w);
    convert_x_pool<<<BB * CDIM, 256>>>(x);

    // hifi qkv: x^T @ h_qkv_w -> [b][4096][384] fp32
    gemm_xt_pipe<<<dim3(32, 6, 8), 256, XT_SMEM>>>(
        xhi, xlo, (long)CDIM * NTOK, WOFF_HQKV, qkv, (long)NTOK * 384, NTOK, 384);
    // lofi q: x^T @ l_q_w -> [b][4096][128] fp32
    gemm_xt_pipe<<<dim3(32, 2, 8), 256, XT_SMEM>>>(
        xhi, xlo, (long)CDIM * NTOK, WOFF_LQ, ql, (long)NTOK * 128, NTOK, 128);
    // lofi kv: pooled^T @ l_kv_w -> [b][1024][256] fp32
    gemm_xt_pipe<<<dim3(8, 4, 8), 256, XT_SMEM>>>(
        phi, plo, (long)CDIM * MPOOL, WOFF_LKV, kvl, (long)MPOOL * 256, MPOOL, 256);

    // attention (emit bf16 hi/lo)
    hifi_attn<<<4096, 256>>>();
    lofi_attn_mma<<<dim3(32, 32), 256>>>();

    // projections, fused concat+transpose into output
    gemm_proj_pipe<<<dim3(32, 2, 8), 256, PJ_SMEM>>>(
        ohhi, ohlo, (long)NTOK * 128, WOFF_HPROJ, h_proj_b, out, 0);
    gemm_proj_pipe<<<dim3(32, 2, 8), 256, PJ_SMEM>>>(
        olhi, ollo, (long)NTOK * 128, WOFF_LPROJ, l_proj_b, out, 128);
}

// round 14
// speedup vs baseline: 1.0883x; 1.0883x over previous
#include <cuda_runtime.h>
#include <cuda_bf16.h>

// ---------------------------------------------------------------------------
// HiLo attention, b=8, dim=256, H=W=64, WS=2, 4+4 heads, head_dim=32
// Round 14 (third submit of R12; broker infra failures): kv GEMM emits bf16
// hi/lo (K: [b][m][128], V: transposed [b][d][m]); lofi attention stages KV
// via double-buffered cp.async with no in-loop conversion. Math == R9.
// ---------------------------------------------------------------------------

#define BB 8
#define CDIM 256
#define NTOK 4096          // 64*64 tokens per batch
#define MPOOL 1024         // 32*32 pooled tokens per batch
#define ATTN_SCALE 0.17677669529663687f   // 32^-0.5

typedef unsigned long long u64;
typedef unsigned int u32;
typedef unsigned short u16;

// fp32 intermediates (attention inputs)
__device__ float g_qkv [BB * NTOK * 384];   // hifi qkv  [b][t][s*128+head*32+d]
__device__ float g_ql  [BB * NTOK * 128];   // lofi q    [b][t][head*32+d]

// bf16 hi/lo operand tensors
__device__ __nv_bfloat16 g_xhi [BB * CDIM * NTOK];   // x       [b][c][t] K-major
__device__ __nv_bfloat16 g_xlo [BB * CDIM * NTOK];
__device__ __nv_bfloat16 g_phi [BB * CDIM * MPOOL];  // pooled  [b][c][m] K-major
__device__ __nv_bfloat16 g_plo [BB * CDIM * MPOOL];
__device__ __nv_bfloat16 g_whi [229376];             // all weights, see offsets
__device__ __nv_bfloat16 g_wlo [229376];
__device__ __nv_bfloat16 g_kvhi[BB * MPOOL * 128];   // lofi K  [b][m][head*32+d]
__device__ __nv_bfloat16 g_kvlo[BB * MPOOL * 128];
__device__ __nv_bfloat16 g_vthi[BB * 128 * MPOOL];   // lofi V^T [b][head*32+d][m]
__device__ __nv_bfloat16 g_vtlo[BB * 128 * MPOOL];
__device__ __nv_bfloat16 g_ohhi[BB * NTOK * 128];    // hifi attn out [b][t][c]
__device__ __nv_bfloat16 g_ohlo[BB * NTOK * 128];
__device__ __nv_bfloat16 g_olhi[BB * NTOK * 128];    // lofi attn out
__device__ __nv_bfloat16 g_ollo[BB * NTOK * 128];

// weight segment offsets in g_whi/g_wlo
#define WOFF_HQKV   0        // 256*384
#define WOFF_LQ     98304    // 256*128
#define WOFF_LKV    131072   // 256*256
#define WOFF_HPROJ  196608   // 128*128
#define WOFF_LPROJ  212992   // 128*128

// ---- helpers ---------------------------------------------------------------
__device__ __forceinline__ void mma_bf16(
    float* c, const u32* a, u32 b0, u32 b1)
{
    asm volatile(
        "mma.sync.aligned.m16n8k16.row.col.f32.bf16.bf16.f32 "
        "{%0,%1,%2,%3}, {%4,%5,%6,%7}, {%8,%9}, {%0,%1,%2,%3};\n"
        : "+f"(c[0]), "+f"(c[1]), "+f"(c[2]), "+f"(c[3])
        : "r"(a[0]), "r"(a[1]), "r"(a[2]), "r"(a[3]), "r"(b0), "r"(b1));
}
// split two floats into packed bf16x2 hi + residual bf16x2 lo (mem order x0,x1)
__device__ __forceinline__ void bf16_split2(float x0, float x1, u32& hi, u32& lo)
{
    asm("cvt.rn.bf16x2.f32 %0, %1, %2;" : "=r"(hi) : "f"(x1), "f"(x0));
    float h0 = __uint_as_float(hi << 16);
    float h1 = __uint_as_float(hi & 0xffff0000u);
    asm("cvt.rn.bf16x2.f32 %0, %1, %2;" : "=r"(lo) : "f"(x1 - h1), "f"(x0 - h0));
}
__device__ __forceinline__ u32 s2u(const void* p) {
    return (u32)__cvta_generic_to_shared(p);
}
__device__ __forceinline__ void ldsm_x4_t(u32& r0, u32& r1, u32& r2, u32& r3, u32 addr)
{
    asm volatile("ldmatrix.sync.aligned.m8n8.x4.trans.shared.b16 "
                 "{%0,%1,%2,%3}, [%4];"
                 : "=r"(r0), "=r"(r1), "=r"(r2), "=r"(r3) : "r"(addr));
}
__device__ __forceinline__ void ldsm_x4(u32& r0, u32& r1, u32& r2, u32& r3, u32 addr)
{
    asm volatile("ldmatrix.sync.aligned.m8n8.x4.shared.b16 "
                 "{%0,%1,%2,%3}, [%4];"
                 : "=r"(r0), "=r"(r1), "=r"(r2), "=r"(r3) : "r"(addr));
}
__device__ __forceinline__ void cp_cg(u32 dst, const void* src)
{
    asm volatile("cp.async.cg.shared.global [%0], [%1], 16;\n"
                 :: "r"(dst), "l"(src));
}
#define CP_COMMIT() asm volatile("cp.async.commit_group;\n")

// ---------------------------------------------------------------------------
// convert x -> bf16 hi/lo and fused 2x2 avg pool -> bf16 hi/lo
// ---------------------------------------------------------------------------
__global__ __launch_bounds__(256) void convert_x_pool(const float* __restrict__ x)
{
    const int bc = blockIdx.x;
    const float* xp = x + (long)bc * 4096;
    __nv_bfloat16* xh = g_xhi + (long)bc * 4096;
    __nv_bfloat16* xl = g_xlo + (long)bc * 4096;
#pragma unroll
    for (int p = 0; p < 4; p++) {
        const int i = threadIdx.x * 4 + p * 1024;
        float4 v = *(const float4*)&xp[i];
        u32 h01, l01, h23, l23;
        bf16_split2(v.x, v.y, h01, l01);
        bf16_split2(v.z, v.w, h23, l23);
        *(u32*)&xh[i] = h01; *(u32*)&xh[i + 2] = h23;
        *(u32*)&xl[i] = l01; *(u32*)&xl[i + 2] = l23;
    }
    __nv_bfloat16* ph = g_phi + (long)bc * 1024;
    __nv_bfloat16* pl = g_plo + (long)bc * 1024;
#pragma unroll
    for (int p = 0; p < 2; p++) {
        const int m = threadIdx.x * 2 + p * 512;
        const int hg = m >> 5, wg = m & 31;
        const float* r0 = xp + hg * 128 + wg * 2;
        float4 a = *(const float4*)&r0[0];
        float4 b = *(const float4*)&r0[64];
        float p0 = 0.25f * (a.x + a.y + b.x + b.y);
        float p1 = 0.25f * (a.z + a.w + b.z + b.w);
        u32 h, l;
        bf16_split2(p0, p1, h, l);
        *(u32*)&ph[m] = h;
        *(u32*)&pl[m] = l;
    }
}

// ---------------------------------------------------------------------------
// convert all 5 weight matrices into g_whi/g_wlo (229376 elems)
// ---------------------------------------------------------------------------
__global__ __launch_bounds__(256) void convert_w(
    const float* __restrict__ w0, const float* __restrict__ w1,
    const float* __restrict__ w2, const float* __restrict__ w3,
    const float* __restrict__ w4)
{
    const long idx = ((long)blockIdx.x * 256 + threadIdx.x) * 4;
    const float* src; long off;
    if (idx < WOFF_LQ)         { src = w0; off = 0; }
    else if (idx < WOFF_LKV)   { src = w1; off = WOFF_LQ; }
    else if (idx < WOFF_HPROJ) { src = w2; off = WOFF_LKV; }
    else if (idx < WOFF_LPROJ) { src = w3; off = WOFF_HPROJ; }
    else                       { src = w4; off = WOFF_LPROJ; }
    float4 v = *(const float4*)&src[idx - off];
    u32 h01, l01, h23, l23;
    bf16_split2(v.x, v.y, h01, l01);
    bf16_split2(v.z, v.w, h23, l23);
    *(u32*)&g_whi[idx] = h01; *(u32*)&g_whi[idx + 2] = h23;
    *(u32*)&g_wlo[idx] = l01; *(u32*)&g_wlo[idx + 2] = l23;
}

// ---------------------------------------------------------------------------
// 3-stage pipelined bf16x3 GEMM, A K-major bf16 hi/lo, fp32 out. (R9)
// K=256, BM=128, BN=64, BK=32, 256 thr (8 warps 4m x 2n).
// ---------------------------------------------------------------------------
#define XT_SMEM 79872
__global__ __launch_bounds__(256, 2) void gemm_xt_pipe(
    const __nv_bfloat16* __restrict__ Ahi, const __nv_bfloat16* __restrict__ Alo,
    long aBatch, int woff,
    float* __restrict__ Cout, long cBatch, int M, int N)
{
    extern __shared__ char smraw[];
    const u32 sbase = s2u(smraw);
#define SA_(st,hl,k,m) (sbase + (((((st)*2+(hl))*32)+(k))*136 + (m))*2)
#define SW_(st,hl,k,n) (sbase + 52224 + (((((st)*2+(hl))*32)+(k))*72 + (n))*2)

    const int tid = threadIdx.x;
    const int wid = tid >> 5;
    const int lane = tid & 31;
    const int m0 = blockIdx.x * 128;
    const int n0 = blockIdx.y * 64;
    const int wm = (wid & 3) * 32;
    const int wn = (wid >> 2) * 32;
    const __nv_bfloat16* Ah = Ahi + (long)blockIdx.z * aBatch + m0;
    const __nv_bfloat16* Al = Alo + (long)blockIdx.z * aBatch + m0;
    const __nv_bfloat16* Wh = g_whi + woff + n0;
    const __nv_bfloat16* Wl = g_wlo + woff + n0;
    float* Cb = Cout + (long)blockIdx.z * cBatch;

    const int l7 = lane & 7;
    const int a_koff = l7 + ((lane & 16) ? 8 : 0);
    const int a_moff = (lane & 8) ? 8 : 0;
    const int b_koff = l7 + ((lane & 8) ? 8 : 0);
    const int b_noff = (lane & 16) ? 8 : 0;

    const int ar0 = tid >> 4,          ac0 = (tid & 15) * 8;
    const int ar1 = (tid + 256) >> 4,  ac1 = ((tid + 256) & 15) * 8;
    const int wr = tid >> 3,           wc = (tid & 7) * 8;

    auto issue_chunk = [&](int st, int chunk) {
        const long kb = (long)chunk * 32;
        cp_cg(SA_(st, 0, ar0, ac0), Ah + (kb + ar0) * M + ac0);
        cp_cg(SA_(st, 1, ar0, ac0), Al + (kb + ar0) * M + ac0);
        cp_cg(SA_(st, 0, ar1, ac1), Ah + (kb + ar1) * M + ac1);
        cp_cg(SA_(st, 1, ar1, ac1), Al + (kb + ar1) * M + ac1);
        cp_cg(SW_(st, 0, wr, wc), Wh + (kb + wr) * N + wc);
        cp_cg(SW_(st, 1, wr, wc), Wl + (kb + wr) * N + wc);
        CP_COMMIT();
    };

    float acc[2][4][4];
#pragma unroll
    for (int i = 0; i < 2; i++)
#pragma unroll
        for (int j = 0; j < 4; j++)
#pragma unroll
            for (int c = 0; c < 4; c++) acc[i][j][c] = 0.f;

    issue_chunk(0, 0);
    issue_chunk(1, 1);

#pragma unroll
    for (int it = 0; it < 8; it++) {
        if (it < 7) asm volatile("cp.async.wait_group 1;\n");
        else        asm volatile("cp.async.wait_group 0;\n");
        __syncthreads();
        if (it + 2 < 8) issue_chunk((it + 2) % 3, it + 2);

        const int st = it % 3;
#pragma unroll
        for (int ks = 0; ks < 2; ks++) {
            const int kk = ks * 16;
            u32 ahi[2][4], alo[2][4];
#pragma unroll
            for (int i = 0; i < 2; i++) {
                const int mb = wm + i * 16;
                ldsm_x4_t(ahi[i][0], ahi[i][1], ahi[i][2], ahi[i][3],
                          SA_(st, 0, kk + a_koff, mb + a_moff));
                ldsm_x4_t(alo[i][0], alo[i][1], alo[i][2], alo[i][3],
                          SA_(st, 1, kk + a_koff, mb + a_moff));
            }
            u32 bhi[4][2], blo[4][2];
#pragma unroll
            for (int np = 0; np < 2; np++) {
                const int nb2 = wn + np * 16;
                u32 r0, r1, r2, r3;
                ldsm_x4_t(r0, r1, r2, r3, SW_(st, 0, kk + b_koff, nb2 + b_noff));
                bhi[2 * np][0] = r0; bhi[2 * np][1] = r1;
                bhi[2 * np + 1][0] = r2; bhi[2 * np + 1][1] = r3;
                ldsm_x4_t(r0, r1, r2, r3, SW_(st, 1, kk + b_koff, nb2 + b_noff));
                blo[2 * np][0] = r0; blo[2 * np][1] = r1;
                blo[2 * np + 1][0] = r2; blo[2 * np + 1][1] = r3;
            }
#pragma unroll
            for (int i = 0; i < 2; i++)
#pragma unroll
                for (int j = 0; j < 4; j++) {
                    mma_bf16(acc[i][j], ahi[i], bhi[j][0], bhi[j][1]);
                    mma_bf16(acc[i][j], alo[i], bhi[j][0], bhi[j][1]);
                    mma_bf16(acc[i][j], ahi[i], blo[j][0], blo[j][1]);
                }
        }
    }

    const int g = lane >> 2, tg = lane & 3;
#pragma unroll
    for (int i = 0; i < 2; i++)
#pragma unroll
        for (int j = 0; j < 4; j++) {
            const int row = m0 + wm + i * 16 + g;
            const int col = n0 + wn + j * 8 + 2 * tg;
            *(float2*)&Cb[(long)row * N + col] =
                make_float2(acc[i][j][0], acc[i][j][1]);
            *(float2*)&Cb[(long)(row + 8) * N + col] =
                make_float2(acc[i][j][2], acc[i][j][3]);
        }
#undef SA_
#undef SW_
}

// ---------------------------------------------------------------------------
// Same GEMM but for lofi KV: emits bf16 hi/lo.
// n<128 (K): g_kvhi/lo[b][m][n];  n>=128 (V): transposed g_vthi/lo[b][n-128][m].
// ---------------------------------------------------------------------------
__global__ __launch_bounds__(256, 2) void gemm_kv_pipe(
    const __nv_bfloat16* __restrict__ Ahi, const __nv_bfloat16* __restrict__ Alo,
    long aBatch)
{
    extern __shared__ char smraw[];
    const u32 sbase = s2u(smraw);
#define SA_(st,hl,k,m) (sbase + (((((st)*2+(hl))*32)+(k))*136 + (m))*2)
#define SW_(st,hl,k,n) (sbase + 52224 + (((((st)*2+(hl))*32)+(k))*72 + (n))*2)
    const int M = MPOOL, N = 256;

    const int tid = threadIdx.x;
    const int wid = tid >> 5;
    const int lane = tid & 31;
    const int m0 = blockIdx.x * 128;
    const int n0 = blockIdx.y * 64;
    const int wm = (wid & 3) * 32;
    const int wn = (wid >> 2) * 32;
    const __nv_bfloat16* Ah = Ahi + (long)blockIdx.z * aBatch + m0;
    const __nv_bfloat16* Al = Alo + (long)blockIdx.z * aBatch + m0;
    const __nv_bfloat16* Wh = g_whi + WOFF_LKV + n0;
    const __nv_bfloat16* Wl = g_wlo + WOFF_LKV + n0;

    const int l7 = lane & 7;
    const int a_koff = l7 + ((lane & 16) ? 8 : 0);
    const int a_moff = (lane & 8) ? 8 : 0;
    const int b_koff = l7 + ((lane & 8) ? 8 : 0);
    const int b_noff = (lane & 16) ? 8 : 0;

    const int ar0 = tid >> 4,          ac0 = (tid & 15) * 8;
    const int ar1 = (tid + 256) >> 4,  ac1 = ((tid + 256) & 15) * 8;
    const int wr = tid >> 3,           wc = (tid & 7) * 8;

    auto issue_chunk = [&](int st, int chunk) {
        const long kb = (long)chunk * 32;
        cp_cg(SA_(st, 0, ar0, ac0), Ah + (kb + ar0) * M + ac0);
        cp_cg(SA_(st, 1, ar0, ac0), Al + (kb + ar0) * M + ac0);
        cp_cg(SA_(st, 0, ar1, ac1), Ah + (kb + ar1) * M + ac1);
        cp_cg(SA_(st, 1, ar1, ac1), Al + (kb + ar1) * M + ac1);
        cp_cg(SW_(st, 0, wr, wc), Wh + (kb + wr) * N + wc);
        cp_cg(SW_(st, 1, wr, wc), Wl + (kb + wr) * N + wc);
        CP_COMMIT();
    };

    float acc[2][4][4];
#pragma unroll
    for (int i = 0; i < 2; i++)
#pragma unroll
        for (int j = 0; j < 4; j++)
#pragma unroll
            for (int c = 0; c < 4; c++) acc[i][j][c] = 0.f;

    issue_chunk(0, 0);
    issue_chunk(1, 1);

#pragma unroll
    for (int it = 0; it < 8; it++) {
        if (it < 7) asm volatile("cp.async.wait_group 1;\n");
        else        asm volatile("cp.async.wait_group 0;\n");
        __syncthreads();
        if (it + 2 < 8) issue_chunk((it + 2) % 3, it + 2);

        const int st = it % 3;
#pragma unroll
        for (int ks = 0; ks < 2; ks++) {
            const int kk = ks * 16;
            u32 ahi[2][4], alo[2][4];
#pragma unroll
            for (int i = 0; i < 2; i++) {
                const int mb = wm + i * 16;
                ldsm_x4_t(ahi[i][0], ahi[i][1], ahi[i][2], ahi[i][3],
                          SA_(st, 0, kk + a_koff, mb + a_moff));
                ldsm_x4_t(alo[i][0], alo[i][1], alo[i][2], alo[i][3],
                          SA_(st, 1, kk + a_koff, mb + a_moff));
            }
            u32 bhi[4][2], blo[4][2];
#pragma unroll
            for (int np = 0; np < 2; np++) {
                const int nb2 = wn + np * 16;
                u32 r0, r1, r2, r3;
                ldsm_x4_t(r0, r1, r2, r3, SW_(st, 0, kk + b_koff, nb2 + b_noff));
                bhi[2 * np][0] = r0; bhi[2 * np][1] = r1;
                bhi[2 * np + 1][0] = r2; bhi[2 * np + 1][1] = r3;
                ldsm_x4_t(r0, r1, r2, r3, SW_(st, 1, kk + b_koff, nb2 + b_noff));
                blo[2 * np][0] = r0; blo[2 * np][1] = r1;
                blo[2 * np + 1][0] = r2; blo[2 * np + 1][1] = r3;
            }
#pragma unroll
            for (int i = 0; i < 2; i++)
#pragma unroll
                for (int j = 0; j < 4; j++) {
                    mma_bf16(acc[i][j], ahi[i], bhi[j][0], bhi[j][1]);
                    mma_bf16(acc[i][j], alo[i], bhi[j][0], bhi[j][1]);
                    mma_bf16(acc[i][j], ahi[i], blo[j][0], blo[j][1]);
                }
        }
    }

    const int g = lane >> 2, tg = lane & 3;
    const int b = blockIdx.z;
#pragma unroll
    for (int i = 0; i < 2; i++)
#pragma unroll
        for (int j = 0; j < 4; j++) {
            const int row = m0 + wm + i * 16 + g;
            const int col = n0 + wn + j * 8 + 2 * tg;
            u32 h0, l0, h1, l1;
            bf16_split2(acc[i][j][0], acc[i][j][1], h0, l0);
            bf16_split2(acc[i][j][2], acc[i][j][3], h1, l1);
            if (col < 128) {
                const long k0i = ((long)(b * MPOOL) + row) * 128 + col;
                const long k1i = ((long)(b * MPOOL) + row + 8) * 128 + col;
                *(u32*)&g_kvhi[k0i] = h0;
                *(u32*)&g_kvlo[k0i] = l0;
                *(u32*)&g_kvhi[k1i] = h1;
                *(u32*)&g_kvlo[k1i] = l1;
            } else {
                const long vb = ((long)(b * 128 + (col - 128))) * MPOOL;
                ((u16*)g_vthi)[vb + row]              = (u16)(h0 & 0xffff);
                ((u16*)g_vthi)[vb + MPOOL + row]      = (u16)(h0 >> 16);
                ((u16*)g_vtlo)[vb + row]              = (u16)(l0 & 0xffff);
                ((u16*)g_vtlo)[vb + MPOOL + row]      = (u16)(l0 >> 16);
                ((u16*)g_vthi)[vb + row + 8]          = (u16)(h1 & 0xffff);
                ((u16*)g_vthi)[vb + MPOOL + row + 8]  = (u16)(h1 >> 16);
                ((u16*)g_vtlo)[vb + row + 8]          = (u16)(l1 & 0xffff);
                ((u16*)g_vtlo)[vb + MPOOL + row + 8]  = (u16)(l1 >> 16);
            }
        }
#undef SA_
#undef SW_
}

// ---------------------------------------------------------------------------
// 3-stage pipelined bf16x3 projection GEMM, K=128, A row-major [M][128]. (R9)
// ---------------------------------------------------------------------------
#define PJ_SMEM 89088
__global__ __launch_bounds__(256, 2) void gemm_proj_pipe(
    const __nv_bfloat16* __restrict__ Ahi, const __nv_bfloat16* __restrict__ Alo,
    long aBatch, int woff,
    const float* __restrict__ bias,
    float* __restrict__ out, int coff)
{
    extern __shared__ char smraw[];
    const u32 sbase = s2u(smraw);
#define SA_(st,hl,m,k) (sbase + (((((st)*2+(hl))*128)+(m))*40 + (k))*2)
#define SW_(st,hl,k,n) (sbase + 61440 + (((((st)*2+(hl))*32)+(k))*72 + (n))*2)

    const int tid = threadIdx.x;
    const int wid = tid >> 5;
    const int lane = tid & 31;
    const int m0 = blockIdx.x * 128;
    const int n0 = blockIdx.y * 64;
    const int wm = (wid & 3) * 32;
    const int wn = (wid >> 2) * 32;
    const __nv_bfloat16* Ah = Ahi + (long)blockIdx.z * aBatch + (long)m0 * 128;
    const __nv_bfloat16* Al = Alo + (long)blockIdx.z * aBatch + (long)m0 * 128;
    const __nv_bfloat16* Wh = g_whi + woff + n0;
    const __nv_bfloat16* Wl = g_wlo + woff + n0;

    const int l7 = lane & 7;
    const int a_moff = l7 + ((lane & 8) ? 8 : 0);
    const int a_koff = (lane & 16) ? 8 : 0;
    const int b_koff = l7 + ((lane & 8) ? 8 : 0);
    const int b_noff = (lane & 16) ? 8 : 0;

    const int ar0 = tid >> 2,          ac0 = (tid & 3) * 8;
    const int ar1 = (tid + 256) >> 2,  ac1 = ((tid + 256) & 3) * 8;
    const int wr = tid >> 3,           wc = (tid & 7) * 8;

    auto issue_chunk = [&](int st, int chunk) {
        const long kb = (long)chunk * 32;
        cp_cg(SA_(st, 0, ar0, ac0), Ah + (long)ar0 * 128 + kb + ac0);
        cp_cg(SA_(st, 1, ar0, ac0), Al + (long)ar0 * 128 + kb + ac0);
        cp_cg(SA_(st, 0, ar1, ac1), Ah + (long)ar1 * 128 + kb + ac1);
        cp_cg(SA_(st, 1, ar1, ac1), Al + (long)ar1 * 128 + kb + ac1);
        cp_cg(SW_(st, 0, wr, wc), Wh + (kb + wr) * 128 + wc);
        cp_cg(SW_(st, 1, wr, wc), Wl + (kb + wr) * 128 + wc);
        CP_COMMIT();
    };

    float acc[2][4][4];
#pragma unroll
    for (int i = 0; i < 2; i++)
#pragma unroll
        for (int j = 0; j < 4; j++)
#pragma unroll
            for (int c = 0; c < 4; c++) acc[i][j][c] = 0.f;

    issue_chunk(0, 0);
    issue_chunk(1, 1);

#pragma unroll
    for (int it = 0; it < 4; it++) {
        if (it < 3) asm volatile("cp.async.wait_group 1;\n");
        else        asm volatile("cp.async.wait_group 0;\n");
        __syncthreads();
        if (it + 2 < 4) issue_chunk((it + 2) % 3, it + 2);

        const int st = it % 3;
#pragma unroll
        for (int ks = 0; ks < 2; ks++) {
            const int kk = ks * 16;
            u32 ahi[2][4], alo[2][4];
#pragma unroll
            for (int i = 0; i < 2; i++) {
                const int mb = wm + i * 16;
                ldsm_x4(ahi[i][0], ahi[i][1], ahi[i][2], ahi[i][3],
                        SA_(st, 0, mb + a_moff, kk + a_koff));
                ldsm_x4(alo[i][0], alo[i][1], alo[i][2], alo[i][3],
                        SA_(st, 1, mb + a_moff, kk + a_koff));
            }
            u32 bhi[4][2], blo[4][2];
#pragma unroll
            for (int np = 0; np < 2; np++) {
                const int nb2 = wn + np * 16;
                u32 r0, r1, r2, r3;
                ldsm_x4_t(r0, r1, r2, r3, SW_(st, 0, kk + b_koff, nb2 + b_noff));
                bhi[2 * np][0] = r0; bhi[2 * np][1] = r1;
                bhi[2 * np + 1][0] = r2; bhi[2 * np + 1][1] = r3;
                ldsm_x4_t(r0, r1, r2, r3, SW_(st, 1, kk + b_koff, nb2 + b_noff));
                blo[2 * np][0] = r0; blo[2 * np][1] = r1;
                blo[2 * np + 1][0] = r2; blo[2 * np + 1][1] = r3;
            }
#pragma unroll
            for (int i = 0; i < 2; i++)
#pragma unroll
                for (int j = 0; j < 4; j++) {
                    mma_bf16(acc[i][j], ahi[i], bhi[j][0], bhi[j][1]);
                    mma_bf16(acc[i][j], alo[i], bhi[j][0], bhi[j][1]);
                    mma_bf16(acc[i][j], ahi[i], blo[j][0], blo[j][1]);
                }
        }
    }

    const int g = lane >> 2, tg = lane & 3;
    float* ob = out + ((long)blockIdx.z * 256 + coff) * 4096;
#pragma unroll
    for (int j = 0; j < 4; j++) {
        const int nl = n0 + wn + j * 8 + 2 * tg;
        const float bv0 = bias[nl];
        const float bv1 = bias[nl + 1];
#pragma unroll
        for (int i = 0; i < 2; i++) {
            const int m = m0 + wm + i * 16 + g;
            ob[(long)nl * 4096 + m]           = acc[i][j][0] + bv0;
            ob[(long)(nl + 1) * 4096 + m]     = acc[i][j][1] + bv1;
            ob[(long)nl * 4096 + m + 8]       = acc[i][j][2] + bv0;
            ob[(long)(nl + 1) * 4096 + m + 8] = acc[i][j][3] + bv1;
        }
    }
#undef SA_
#undef SW_
}

// ---------------------------------------------------------------------------
// hifi window attention: one warp per (b, window, head); emits bf16 hi/lo.
// ---------------------------------------------------------------------------
__global__ __launch_bounds__(256) void hifi_attn()
{
    const int wid = (blockIdx.x * blockDim.x + threadIdx.x) >> 5;
    const int lane = threadIdx.x & 31;
    const int head = wid & 3;
    const int win = (wid >> 2) & 1023;
    const int b = wid >> 12;
    const int hg = win >> 5, wgc = win & 31;

    float q[4], k[4], v[4];
    int t[4];
#pragma unroll
    for (int i = 0; i < 4; i++) {
        const int r = 2 * hg + (i >> 1);
        const int c = 2 * wgc + (i & 1);
        t[i] = r * 64 + c;
        const float* base = g_qkv + (long)(b * NTOK + t[i]) * 384 + head * 32 + lane;
        q[i] = base[0];
        k[i] = base[128];
        v[i] = base[256];
    }
    float s[4][4];
#pragma unroll
    for (int i = 0; i < 4; i++)
#pragma unroll
        for (int j = 0; j < 4; j++) {
            float p = q[i] * k[j];
#pragma unroll
            for (int off = 16; off; off >>= 1)
                p += __shfl_xor_sync(0xffffffffu, p, off);
            s[i][j] = p * ATTN_SCALE;
        }
#pragma unroll
    for (int i = 0; i < 4; i++) {
        float mx = fmaxf(fmaxf(s[i][0], s[i][1]), fmaxf(s[i][2], s[i][3]));
        float e0 = __expf(s[i][0] - mx);
        float e1 = __expf(s[i][1] - mx);
        float e2 = __expf(s[i][2] - mx);
        float e3 = __expf(s[i][3] - mx);
        float inv = 1.0f / (e0 + e1 + e2 + e3);
        float o = (e0 * v[0] + e1 * v[1] + e2 * v[2] + e3 * v[3]) * inv;
        const long idx = (long)(b * NTOK + t[i]) * 128 + head * 32 + lane;
        __nv_bfloat16 h = __float2bfloat16(o);
        g_ohhi[idx] = h;
        g_ohlo[idx] = __float2bfloat16(o - __bfloat162float(h));
    }
}

// ---------------------------------------------------------------------------
// lofi flash attention (bf16x3, m16n8k16), KV pre-split: staging is pure
// double-buffered cp.async (no conversion, no transpose). Emits bf16 hi/lo.
// Smem per stage: Khi 64x40 + Klo 64x40 + Vhi 32x72 + Vlo 32x72 bf16 = 19456 B.
// ---------------------------------------------------------------------------
#define LST 19456
#define LKH 0
#define LKL 5120
#define LVH 10240
#define LVL 14848
__global__ __launch_bounds__(256, 2) void lofi_attn_mma()
{
    __shared__ __align__(16) char smv[2][LST];

    const int tid = threadIdx.x;
    const int lane = tid & 31;
    const int warp = tid >> 5;
    const int g = lane >> 2;
    const int tg = lane & 3;
    const int bh = blockIdx.y;
    const int b = bh >> 2, head = bh & 3;
    const int qrow0 = blockIdx.x * 128 + warp * 16;

    const __nv_bfloat16* kh = g_kvhi + (long)(b * MPOOL) * 128 + head * 32;
    const __nv_bfloat16* kl = g_kvlo + (long)(b * MPOOL) * 128 + head * 32;
    const __nv_bfloat16* vh = g_vthi + (long)(b * 128 + head * 32) * MPOOL;
    const __nv_bfloat16* vl = g_vtlo + (long)(b * 128 + head * 32) * MPOOL;

    auto fill = [&](int st, int j0) {
        const u32 base = s2u(smv[st]);
        {   // K: 64 rows x 32 dims, hi + lo
            const int r = tid >> 2, gc = tid & 3;
            cp_cg(base + LKH + r * 80 + gc * 16, kh + (long)(j0 + r) * 128 + gc * 8);
            cp_cg(base + LKL + r * 80 + gc * 16, kl + (long)(j0 + r) * 128 + gc * 8);
        }
        {   // V^T: 32 d-rows x 64 kv, hi + lo
            const int r = tid >> 3, gc = tid & 7;
            cp_cg(base + LVH + r * 144 + gc * 16, vh + (long)r * MPOOL + j0 + gc * 8);
            cp_cg(base + LVL + r * 144 + gc * 16, vl + (long)r * MPOOL + j0 + gc * 8);
        }
        CP_COMMIT();
    };

    // Q fragments (loop-invariant), pre-scaled, bf16 hi/lo split
    const float* qbase = g_ql + ((long)(b * NTOK + qrow0)) * 128 + head * 32;
    u32 qa_hi[2][4], qa_lo[2][4];
#pragma unroll
    for (int kt = 0; kt < 2; kt++) {
        float2 f0 = *(const float2*)&qbase[(long)g * 128 + kt * 16 + 2 * tg];
        float2 f1 = *(const float2*)&qbase[(long)(g + 8) * 128 + kt * 16 + 2 * tg];
        float2 f2 = *(const float2*)&qbase[(long)g * 128 + kt * 16 + 8 + 2 * tg];
        float2 f3 = *(const float2*)&qbase[(long)(g + 8) * 128 + kt * 16 + 8 + 2 * tg];
        bf16_split2(f0.x * ATTN_SCALE, f0.y * ATTN_SCALE, qa_hi[kt][0], qa_lo[kt][0]);
        bf16_split2(f1.x * ATTN_SCALE, f1.y * ATTN_SCALE, qa_hi[kt][1], qa_lo[kt][1]);
        bf16_split2(f2.x * ATTN_SCALE, f2.y * ATTN_SCALE, qa_hi[kt][2], qa_lo[kt][2]);
        bf16_split2(f3.x * ATTN_SCALE, f3.y * ATTN_SCALE, qa_hi[kt][3], qa_lo[kt][3]);
    }

    float od[4][4];
#pragma unroll
    for (int dt = 0; dt < 4; dt++)
#pragma unroll
        for (int c = 0; c < 4; c++) od[dt][c] = 0.f;
    float mrow[2] = {-1e30f, -1e30f};
    float lrow[2] = {0.f, 0.f};

    fill(0, 0);

    for (int c = 0; c < 16; c++) {
        if (c + 1 < 16) {
            fill((c + 1) & 1, (c + 1) * 64);
            asm volatile("cp.async.wait_group 1;\n");
        } else {
            asm volatile("cp.async.wait_group 0;\n");
        }
        __syncthreads();

        const char* sb = smv[c & 1];
        const char* sKhiB = sb + LKH;
        const char* sKloB = sb + LKL;
        const char* sVhiB = sb + LVH;
        const char* sVloB = sb + LVL;

        // --- QK^T: 8 n-tiles of 8 kv cols, bf16x3 ---
        float s[8][4];
#pragma unroll
        for (int nt = 0; nt < 8; nt++) {
            float cc[4] = {0.f, 0.f, 0.f, 0.f};
            const int kv = nt * 8 + g;
#pragma unroll
            for (int kt = 0; kt < 2; kt++) {
                const int kk = kt * 16;
                u32 bh0 = *(const u32*)(sKhiB + kv * 80 + (kk + 2 * tg) * 2);
                u32 bh1 = *(const u32*)(sKhiB + kv * 80 + (kk + 8 + 2 * tg) * 2);
                u32 bl0 = *(const u32*)(sKloB + kv * 80 + (kk + 2 * tg) * 2);
                u32 bl1 = *(const u32*)(sKloB + kv * 80 + (kk + 8 + 2 * tg) * 2);
                mma_bf16(cc, qa_hi[kt], bh0, bh1);
                mma_bf16(cc, qa_lo[kt], bh0, bh1);
                mma_bf16(cc, qa_hi[kt], bl0, bl1);
            }
            s[nt][0] = cc[0]; s[nt][1] = cc[1]; s[nt][2] = cc[2]; s[nt][3] = cc[3];
        }

        // --- online softmax (rows g and g+8) ---
        float mx0 = s[0][0], mx1 = s[0][2];
#pragma unroll
        for (int nt = 0; nt < 8; nt++) {
            mx0 = fmaxf(mx0, fmaxf(s[nt][0], s[nt][1]));
            mx1 = fmaxf(mx1, fmaxf(s[nt][2], s[nt][3]));
        }
        mx0 = fmaxf(mx0, __shfl_xor_sync(0xffffffffu, mx0, 1));
        mx0 = fmaxf(mx0, __shfl_xor_sync(0xffffffffu, mx0, 2));
        mx1 = fmaxf(mx1, __shfl_xor_sync(0xffffffffu, mx1, 1));
        mx1 = fmaxf(mx1, __shfl_xor_sync(0xffffffffu, mx1, 2));

        const float mn0 = fmaxf(mrow[0], mx0);
        const float mn1 = fmaxf(mrow[1], mx1);
        const float sf0 = __expf(mrow[0] - mn0);
        const float sf1 = __expf(mrow[1] - mn1);
        mrow[0] = mn0; mrow[1] = mn1;
        lrow[0] *= sf0; lrow[1] *= sf1;
#pragma unroll
        for (int dt = 0; dt < 4; dt++) {
            od[dt][0] *= sf0; od[dt][1] *= sf0;
            od[dt][2] *= sf1; od[dt][3] *= sf1;
        }
#pragma unroll
        for (int nt = 0; nt < 8; nt++) {
            s[nt][0] = __expf(s[nt][0] - mn0);
            s[nt][1] = __expf(s[nt][1] - mn0);
            s[nt][2] = __expf(s[nt][2] - mn1);
            s[nt][3] = __expf(s[nt][3] - mn1);
            lrow[0] += s[nt][0] + s[nt][1];
            lrow[1] += s[nt][2] + s[nt][3];
        }

        // --- PV: 4 k-tiles of 16 kv, 4 d-tiles of 8, bf16x3 ---
#pragma unroll
        for (int kt2 = 0; kt2 < 4; kt2++) {
            u32 pa_hi[4], pa_lo[4];
            bf16_split2(s[2 * kt2][0],     s[2 * kt2][1],     pa_hi[0], pa_lo[0]);
            bf16_split2(s[2 * kt2][2],     s[2 * kt2][3],     pa_hi[1], pa_lo[1]);
            bf16_split2(s[2 * kt2 + 1][0], s[2 * kt2 + 1][1], pa_hi[2], pa_lo[2]);
            bf16_split2(s[2 * kt2 + 1][2], s[2 * kt2 + 1][3], pa_hi[3], pa_lo[3]);
            const int kv0 = kt2 * 16;
#pragma unroll
            for (int dt = 0; dt < 4; dt++) {
                const int d = dt * 8 + g;
                u32 vb_h0 = *(const u32*)(sVhiB + d * 144 + (kv0 + 2 * tg) * 2);
                u32 vb_h1 = *(const u32*)(sVhiB + d * 144 + (kv0 + 8 + 2 * tg) * 2);
                u32 vb_l0 = *(const u32*)(sVloB + d * 144 + (kv0 + 2 * tg) * 2);
                u32 vb_l1 = *(const u32*)(sVloB + d * 144 + (kv0 + 8 + 2 * tg) * 2);
                mma_bf16(od[dt], pa_hi, vb_h0, vb_h1);
                mma_bf16(od[dt], pa_lo, vb_h0, vb_h1);
                mma_bf16(od[dt], pa_hi, vb_l0, vb_l1);
            }
        }
        __syncthreads();
    }

    lrow[0] += __shfl_xor_sync(0xffffffffu, lrow[0], 1);
    lrow[0] += __shfl_xor_sync(0xffffffffu, lrow[0], 2);
    lrow[1] += __shfl_xor_sync(0xffffffffu, lrow[1], 1);
    lrow[1] += __shfl_xor_sync(0xffffffffu, lrow[1], 2);
    const float inv0 = 1.0f / lrow[0];
    const float inv1 = 1.0f / lrow[1];

    const long obase = ((long)(b * NTOK + qrow0)) * 128 + head * 32;
#pragma unroll
    for (int dt = 0; dt < 4; dt++) {
        const int col = dt * 8 + 2 * tg;
        u32 h, l;
        bf16_split2(od[dt][0] * inv0, od[dt][1] * inv0, h, l);
        *(u32*)&g_olhi[obase + (long)g * 128 + col] = h;
        *(u32*)&g_ollo[obase + (long)g * 128 + col] = l;
        bf16_split2(od[dt][2] * inv1, od[dt][3] * inv1, h, l);
        *(u32*)&g_olhi[obase + (long)(g + 8) * 128 + col] = h;
        *(u32*)&g_ollo[obase + (long)(g + 8) * 128 + col] = l;
    }
}

// ---------------------------------------------------------------------------
extern "C" void kernel_launch(void* const* d_in, const int* in_sizes, int n_in,
                              void* d_out, int out_size)
{
    const float* x        = (const float*)d_in[0];
    const float* l_q_w    = (const float*)d_in[1];
    const float* l_kv_w   = (const float*)d_in[2];
    const float* l_proj_w = (const float*)d_in[3];
    const float* l_proj_b = (const float*)d_in[4];
    const float* h_qkv_w  = (const float*)d_in[5];
    const float* h_proj_w = (const float*)d_in[6];
    const float* h_proj_b = (const float*)d_in[7];
    float* out = (float*)d_out;

    cudaFuncSetAttribute(gemm_xt_pipe,
                         cudaFuncAttributeMaxDynamicSharedMemorySize, XT_SMEM);
    cudaFuncSetAttribute(gemm_kv_pipe,
                         cudaFuncAttributeMaxDynamicSharedMemorySize, XT_SMEM);
    cudaFuncSetAttribute(gemm_proj_pipe,
                         cudaFuncAttributeMaxDynamicSharedMemorySize, PJ_SMEM);

    float *qkv, *ql;
    __nv_bfloat16 *xhi, *xlo, *phi, *plo, *ohhi, *ohlo, *olhi, *ollo;
    cudaGetSymbolAddress((void**)&qkv,  g_qkv);
    cudaGetSymbolAddress((void**)&ql,   g_ql);
    cudaGetSymbolAddress((void**)&xhi,  g_xhi);
    cudaGetSymbolAddress((void**)&xlo,  g_xlo);
    cudaGetSymbolAddress((void**)&phi,  g_phi);
    cudaGetSymbolAddress((void**)&plo,  g_plo);
    cudaGetSymbolAddress((void**)&ohhi, g_ohhi);
    cudaGetSymbolAddress((void**)&ohlo, g_ohlo);
    cudaGetSymbolAddress((void**)&olhi, g_olhi);
    cudaGetSymbolAddress((void**)&ollo, g_ollo);

    // operand conversion
    convert_w<<<224, 256>>>(h_qkv_w, l_q_w, l_kv_w, h_proj_w, l_proj_w);
    convert_x_pool<<<BB * CDIM, 256>>>(x);

    // hifi qkv: x^T @ h_qkv_w -> [b][4096][384] fp32
    gemm_xt_pipe<<<dim3(32, 6, 8), 256, XT_SMEM>>>(
        xhi, xlo, (long)CDIM * NTOK, WOFF_HQKV, qkv, (long)NTOK * 384, NTOK, 384);
    // lofi q: x^T @ l_q_w -> [b][4096][128] fp32
    gemm_xt_pipe<<<dim3(32, 2, 8), 256, XT_SMEM>>>(
        xhi, xlo, (long)CDIM * NTOK, WOFF_LQ, ql, (long)NTOK * 128, NTOK, 128);
    // lofi kv: pooled^T @ l_kv_w -> bf16 hi/lo (K direct, V transposed)
    gemm_kv_pipe<<<dim3(8, 4, 8), 256, XT_SMEM>>>(phi, plo, (long)CDIM * MPOOL);

    // attention (emit bf16 hi/lo)
    hifi_attn<<<4096, 256>>>();
    lofi_attn_mma<<<dim3(32, 32), 256>>>();

    // projections, fused concat+transpose into output
    gemm_proj_pipe<<<dim3(32, 2, 8), 256, PJ_SMEM>>>(
        ohhi, ohlo, (long)NTOK * 128, WOFF_HPROJ, h_proj_b, out, 0);
    gemm_proj_pipe<<<dim3(32, 2, 8), 256, PJ_SMEM>>>(
        olhi, ollo, (long)NTOK * 128, WOFF_LPROJ, l_proj_b, out, 128);
}

// round 16
// speedup vs baseline: 1.1889x; 1.0925x over previous
#include <cuda_runtime.h>
#include <cuda_bf16.h>
#include <cuda_fp16.h>

// ---------------------------------------------------------------------------
// HiLo attention, b=8, dim=256, H=W=64, WS=2, 4+4 heads, head_dim=32
// Round 16 (R15 resubmit; broker infra failure): GEMMs fp16x2 (A = fp16
// hi+lo, W = fp16 hi only; 2 MMA passes). Attention internals stay bf16x3;
// attention outputs emitted as fp16 hi/lo for the proj GEMM.
// ---------------------------------------------------------------------------

#define BB 8
#define CDIM 256
#define NTOK 4096          // 64*64 tokens per batch
#define MPOOL 1024         // 32*32 pooled tokens per batch
#define ATTN_SCALE 0.17677669529663687f   // 32^-0.5

typedef unsigned long long u64;
typedef unsigned int u32;
typedef unsigned short u16;

// fp32 intermediates (attention inputs)
__device__ float g_qkv [BB * NTOK * 384];   // hifi qkv  [b][t][s*128+head*32+d]
__device__ float g_ql  [BB * NTOK * 128];   // lofi q    [b][t][head*32+d]

// 16-bit operand tensors (raw 16-bit storage; fp16 or bf16 per comment)
__device__ __nv_bfloat16 g_xhi [BB * CDIM * NTOK];   // x fp16 hi [b][c][t]
__device__ __nv_bfloat16 g_xlo [BB * CDIM * NTOK];   // x fp16 lo
__device__ __nv_bfloat16 g_phi [BB * CDIM * MPOOL];  // pooled fp16 hi [b][c][m]
__device__ __nv_bfloat16 g_plo [BB * CDIM * MPOOL];  // pooled fp16 lo
__device__ __nv_bfloat16 g_whi [229376];             // weights fp16 hi (all 5)
__device__ __nv_bfloat16 g_kvhi[BB * MPOOL * 128];   // lofi K bf16 hi [b][m][hd]
__device__ __nv_bfloat16 g_kvlo[BB * MPOOL * 128];   // lofi K bf16 lo
__device__ __nv_bfloat16 g_vthi[BB * 128 * MPOOL];   // lofi V^T bf16 hi [b][d][m]
__device__ __nv_bfloat16 g_vtlo[BB * 128 * MPOOL];   // lofi V^T bf16 lo
__device__ __nv_bfloat16 g_ohhi[BB * NTOK * 128];    // hifi out fp16 hi [b][t][c]
__device__ __nv_bfloat16 g_ohlo[BB * NTOK * 128];    // hifi out fp16 lo
__device__ __nv_bfloat16 g_olhi[BB * NTOK * 128];    // lofi out fp16 hi
__device__ __nv_bfloat16 g_ollo[BB * NTOK * 128];    // lofi out fp16 lo

// weight segment offsets in g_whi
#define WOFF_HQKV   0        // 256*384
#define WOFF_LQ     98304    // 256*128
#define WOFF_LKV    131072   // 256*256
#define WOFF_HPROJ  196608   // 128*128
#define WOFF_LPROJ  212992   // 128*128

// ---- helpers ---------------------------------------------------------------
__device__ __forceinline__ void mma_bf16(
    float* c, const u32* a, u32 b0, u32 b1)
{
    asm volatile(
        "mma.sync.aligned.m16n8k16.row.col.f32.bf16.bf16.f32 "
        "{%0,%1,%2,%3}, {%4,%5,%6,%7}, {%8,%9}, {%0,%1,%2,%3};\n"
        : "+f"(c[0]), "+f"(c[1]), "+f"(c[2]), "+f"(c[3])
        : "r"(a[0]), "r"(a[1]), "r"(a[2]), "r"(a[3]), "r"(b0), "r"(b1));
}
__device__ __forceinline__ void mma_f16(
    float* c, const u32* a, u32 b0, u32 b1)
{
    asm volatile(
        "mma.sync.aligned.m16n8k16.row.col.f32.f16.f16.f32 "
        "{%0,%1,%2,%3}, {%4,%5,%6,%7}, {%8,%9}, {%0,%1,%2,%3};\n"
        : "+f"(c[0]), "+f"(c[1]), "+f"(c[2]), "+f"(c[3])
        : "r"(a[0]), "r"(a[1]), "r"(a[2]), "r"(a[3]), "r"(b0), "r"(b1));
}
// bf16 split (attention path): packed bf16x2 hi + residual lo (mem order x0,x1)
__device__ __forceinline__ void bf16_split2(float x0, float x1, u32& hi, u32& lo)
{
    asm("cvt.rn.bf16x2.f32 %0, %1, %2;" : "=r"(hi) : "f"(x1), "f"(x0));
    float h0 = __uint_as_float(hi << 16);
    float h1 = __uint_as_float(hi & 0xffff0000u);
    asm("cvt.rn.bf16x2.f32 %0, %1, %2;" : "=r"(lo) : "f"(x1 - h1), "f"(x0 - h0));
}
// fp16 split (GEMM path): packed f16x2 hi + residual lo (mem order x0,x1)
__device__ __forceinline__ void f16_split2(float x0, float x1, u32& hi, u32& lo)
{
    asm("cvt.rn.f16x2.f32 %0, %1, %2;" : "=r"(hi) : "f"(x1), "f"(x0));
    float h0, h1;
    asm("{\n\t.reg .f16 a,b;\n\t"
        "mov.b32 {a,b}, %2;\n\t"
        "cvt.f32.f16 %0, a;\n\t"
        "cvt.f32.f16 %1, b;\n\t}"
        : "=f"(h0), "=f"(h1) : "r"(hi));
    asm("cvt.rn.f16x2.f32 %0, %1, %2;" : "=r"(lo) : "f"(x1 - h1), "f"(x0 - h0));
}
__device__ __forceinline__ u32 f16_hi2(float x0, float x1)
{
    u32 h;
    asm("cvt.rn.f16x2.f32 %0, %1, %2;" : "=r"(h) : "f"(x1), "f"(x0));
    return h;
}
__device__ __forceinline__ u32 s2u(const void* p) {
    return (u32)__cvta_generic_to_shared(p);
}
__device__ __forceinline__ void ldsm_x4_t(u32& r0, u32& r1, u32& r2, u32& r3, u32 addr)
{
    asm volatile("ldmatrix.sync.aligned.m8n8.x4.trans.shared.b16 "
                 "{%0,%1,%2,%3}, [%4];"
                 : "=r"(r0), "=r"(r1), "=r"(r2), "=r"(r3) : "r"(addr));
}
__device__ __forceinline__ void ldsm_x4(u32& r0, u32& r1, u32& r2, u32& r3, u32 addr)
{
    asm volatile("ldmatrix.sync.aligned.m8n8.x4.shared.b16 "
                 "{%0,%1,%2,%3}, [%4];"
                 : "=r"(r0), "=r"(r1), "=r"(r2), "=r"(r3) : "r"(addr));
}
__device__ __forceinline__ void cp_cg(u32 dst, const void* src)
{
    asm volatile("cp.async.cg.shared.global [%0], [%1], 16;\n"
                 :: "r"(dst), "l"(src));
}
#define CP_COMMIT() asm volatile("cp.async.commit_group;\n")

// ---------------------------------------------------------------------------
// convert x -> fp16 hi/lo and fused 2x2 avg pool -> fp16 hi/lo
// ---------------------------------------------------------------------------
__global__ __launch_bounds__(256) void convert_x_pool(const float* __restrict__ x)
{
    const int bc = blockIdx.x;
    const float* xp = x + (long)bc * 4096;
    __nv_bfloat16* xh = g_xhi + (long)bc * 4096;
    __nv_bfloat16* xl = g_xlo + (long)bc * 4096;
#pragma unroll
    for (int p = 0; p < 4; p++) {
        const int i = threadIdx.x * 4 + p * 1024;
        float4 v = *(const float4*)&xp[i];
        u32 h01, l01, h23, l23;
        f16_split2(v.x, v.y, h01, l01);
        f16_split2(v.z, v.w, h23, l23);
        *(u32*)&xh[i] = h01; *(u32*)&xh[i + 2] = h23;
        *(u32*)&xl[i] = l01; *(u32*)&xl[i + 2] = l23;
    }
    __nv_bfloat16* ph = g_phi + (long)bc * 1024;
    __nv_bfloat16* pl = g_plo + (long)bc * 1024;
#pragma unroll
    for (int p = 0; p < 2; p++) {
        const int m = threadIdx.x * 2 + p * 512;
        const int hg = m >> 5, wg = m & 31;
        const float* r0 = xp + hg * 128 + wg * 2;
        float4 a = *(const float4*)&r0[0];
        float4 b = *(const float4*)&r0[64];
        float p0 = 0.25f * (a.x + a.y + b.x + b.y);
        float p1 = 0.25f * (a.z + a.w + b.z + b.w);
        u32 h, l;
        f16_split2(p0, p1, h, l);
        *(u32*)&ph[m] = h;
        *(u32*)&pl[m] = l;
    }
}

// ---------------------------------------------------------------------------
// convert all 5 weight matrices into g_whi (fp16 hi only)
// ---------------------------------------------------------------------------
__global__ __launch_bounds__(256) void convert_w(
    const float* __restrict__ w0, const float* __restrict__ w1,
    const float* __restrict__ w2, const float* __restrict__ w3,
    const float* __restrict__ w4)
{
    const long idx = ((long)blockIdx.x * 256 + threadIdx.x) * 4;
    const float* src; long off;
    if (idx < WOFF_LQ)         { src = w0; off = 0; }
    else if (idx < WOFF_LKV)   { src = w1; off = WOFF_LQ; }
    else if (idx < WOFF_HPROJ) { src = w2; off = WOFF_LKV; }
    else if (idx < WOFF_LPROJ) { src = w3; off = WOFF_HPROJ; }
    else                       { src = w4; off = WOFF_LPROJ; }
    float4 v = *(const float4*)&src[idx - off];
    *(u32*)&g_whi[idx]     = f16_hi2(v.x, v.y);
    *(u32*)&g_whi[idx + 2] = f16_hi2(v.z, v.w);
}

// ---------------------------------------------------------------------------
// 3-stage pipelined fp16x2 GEMM, A K-major fp16 hi/lo, W fp16 hi, fp32 out.
// K=256, BM=128, BN=64, BK=32, 256 thr (8 warps 4m x 2n).
// Smem/stage: A 2x32x136 + W 32x72 fp16 = 22016 B; 3 stages = 66048 B.
// ---------------------------------------------------------------------------
#define XT_SMEM 66048
__global__ __launch_bounds__(256, 2) void gemm_xt_pipe(
    const __nv_bfloat16* __restrict__ Ahi, const __nv_bfloat16* __restrict__ Alo,
    long aBatch, int woff,
    float* __restrict__ Cout, long cBatch, int M, int N)
{
    extern __shared__ char smraw[];
    const u32 sbase = s2u(smraw);
#define SA_(st,hl,k,m) (sbase + (st)*22016 + ((((hl)*32)+(k))*136 + (m))*2)
#define SW_(st,k,n)    (sbase + (st)*22016 + 17408 + ((k)*72 + (n))*2)

    const int tid = threadIdx.x;
    const int wid = tid >> 5;
    const int lane = tid & 31;
    const int m0 = blockIdx.x * 128;
    const int n0 = blockIdx.y * 64;
    const int wm = (wid & 3) * 32;
    const int wn = (wid >> 2) * 32;
    const __nv_bfloat16* Ah = Ahi + (long)blockIdx.z * aBatch + m0;
    const __nv_bfloat16* Al = Alo + (long)blockIdx.z * aBatch + m0;
    const __nv_bfloat16* Wh = g_whi + woff + n0;
    float* Cb = Cout + (long)blockIdx.z * cBatch;

    const int l7 = lane & 7;
    const int a_koff = l7 + ((lane & 16) ? 8 : 0);
    const int a_moff = (lane & 8) ? 8 : 0;
    const int b_koff = l7 + ((lane & 8) ? 8 : 0);
    const int b_noff = (lane & 16) ? 8 : 0;

    const int ar0 = tid >> 4,          ac0 = (tid & 15) * 8;
    const int ar1 = (tid + 256) >> 4,  ac1 = ((tid + 256) & 15) * 8;
    const int wr = tid >> 3,           wc = (tid & 7) * 8;

    auto issue_chunk = [&](int st, int chunk) {
        const long kb = (long)chunk * 32;
        cp_cg(SA_(st, 0, ar0, ac0), Ah + (kb + ar0) * M + ac0);
        cp_cg(SA_(st, 1, ar0, ac0), Al + (kb + ar0) * M + ac0);
        cp_cg(SA_(st, 0, ar1, ac1), Ah + (kb + ar1) * M + ac1);
        cp_cg(SA_(st, 1, ar1, ac1), Al + (kb + ar1) * M + ac1);
        cp_cg(SW_(st, wr, wc), Wh + (kb + wr) * N + wc);
        CP_COMMIT();
    };

    float acc[2][4][4];
#pragma unroll
    for (int i = 0; i < 2; i++)
#pragma unroll
        for (int j = 0; j < 4; j++)
#pragma unroll
            for (int c = 0; c < 4; c++) acc[i][j][c] = 0.f;

    issue_chunk(0, 0);
    issue_chunk(1, 1);

#pragma unroll
    for (int it = 0; it < 8; it++) {
        if (it < 7) asm volatile("cp.async.wait_group 1;\n");
        else        asm volatile("cp.async.wait_group 0;\n");
        __syncthreads();
        if (it + 2 < 8) issue_chunk((it + 2) % 3, it + 2);

        const int st = it % 3;
#pragma unroll
        for (int ks = 0; ks < 2; ks++) {
            const int kk = ks * 16;
            u32 ahi[2][4], alo[2][4];
#pragma unroll
            for (int i = 0; i < 2; i++) {
                const int mb = wm + i * 16;
                ldsm_x4_t(ahi[i][0], ahi[i][1], ahi[i][2], ahi[i][3],
                          SA_(st, 0, kk + a_koff, mb + a_moff));
                ldsm_x4_t(alo[i][0], alo[i][1], alo[i][2], alo[i][3],
                          SA_(st, 1, kk + a_koff, mb + a_moff));
            }
            u32 bhi[4][2];
#pragma unroll
            for (int np = 0; np < 2; np++) {
                const int nb2 = wn + np * 16;
                u32 r0, r1, r2, r3;
                ldsm_x4_t(r0, r1, r2, r3, SW_(st, kk + b_koff, nb2 + b_noff));
                bhi[2 * np][0] = r0; bhi[2 * np][1] = r1;
                bhi[2 * np + 1][0] = r2; bhi[2 * np + 1][1] = r3;
            }
#pragma unroll
            for (int i = 0; i < 2; i++)
#pragma unroll
                for (int j = 0; j < 4; j++) {
                    mma_f16(acc[i][j], ahi[i], bhi[j][0], bhi[j][1]);
                    mma_f16(acc[i][j], alo[i], bhi[j][0], bhi[j][1]);
                }
        }
    }

    const int g = lane >> 2, tg = lane & 3;
#pragma unroll
    for (int i = 0; i < 2; i++)
#pragma unroll
        for (int j = 0; j < 4; j++) {
            const int row = m0 + wm + i * 16 + g;
            const int col = n0 + wn + j * 8 + 2 * tg;
            *(float2*)&Cb[(long)row * N + col] =
                make_float2(acc[i][j][0], acc[i][j][1]);
            *(float2*)&Cb[(long)(row + 8) * N + col] =
                make_float2(acc[i][j][2], acc[i][j][3]);
        }
#undef SA_
#undef SW_
}

// ---------------------------------------------------------------------------
// Same fp16x2 GEMM for lofi KV: emits bf16 hi/lo for the attention kernel.
// n<128 (K): g_kvhi/lo[b][m][n];  n>=128 (V): transposed g_vthi/lo[b][n-128][m].
// ---------------------------------------------------------------------------
__global__ __launch_bounds__(256, 2) void gemm_kv_pipe(
    const __nv_bfloat16* __restrict__ Ahi, const __nv_bfloat16* __restrict__ Alo,
    long aBatch)
{
    extern __shared__ char smraw[];
    const u32 sbase = s2u(smraw);
#define SA_(st,hl,k,m) (sbase + (st)*22016 + ((((hl)*32)+(k))*136 + (m))*2)
#define SW_(st,k,n)    (sbase + (st)*22016 + 17408 + ((k)*72 + (n))*2)
    const int M = MPOOL, N = 256;

    const int tid = threadIdx.x;
    const int wid = tid >> 5;
    const int lane = tid & 31;
    const int m0 = blockIdx.x * 128;
    const int n0 = blockIdx.y * 64;
    const int wm = (wid & 3) * 32;
    const int wn = (wid >> 2) * 32;
    const __nv_bfloat16* Ah = Ahi + (long)blockIdx.z * aBatch + m0;
    const __nv_bfloat16* Al = Alo + (long)blockIdx.z * aBatch + m0;
    const __nv_bfloat16* Wh = g_whi + WOFF_LKV + n0;

    const int l7 = lane & 7;
    const int a_koff = l7 + ((lane & 16) ? 8 : 0);
    const int a_moff = (lane & 8) ? 8 : 0;
    const int b_koff = l7 + ((lane & 8) ? 8 : 0);
    const int b_noff = (lane & 16) ? 8 : 0;

    const int ar0 = tid >> 4,          ac0 = (tid & 15) * 8;
    const int ar1 = (tid + 256) >> 4,  ac1 = ((tid + 256) & 15) * 8;
    const int wr = tid >> 3,           wc = (tid & 7) * 8;

    auto issue_chunk = [&](int st, int chunk) {
        const long kb = (long)chunk * 32;
        cp_cg(SA_(st, 0, ar0, ac0), Ah + (kb + ar0) * M + ac0);
        cp_cg(SA_(st, 1, ar0, ac0), Al + (kb + ar0) * M + ac0);
        cp_cg(SA_(st, 0, ar1, ac1), Ah + (kb + ar1) * M + ac1);
        cp_cg(SA_(st, 1, ar1, ac1), Al + (kb + ar1) * M + ac1);
        cp_cg(SW_(st, wr, wc), Wh + (kb + wr) * N + wc);
        CP_COMMIT();
    };

    float acc[2][4][4];
#pragma unroll
    for (int i = 0; i < 2; i++)
#pragma unroll
        for (int j = 0; j < 4; j++)
#pragma unroll
            for (int c = 0; c < 4; c++) acc[i][j][c] = 0.f;

    issue_chunk(0, 0);
    issue_chunk(1, 1);

#pragma unroll
    for (int it = 0; it < 8; it++) {
        if (it < 7) asm volatile("cp.async.wait_group 1;\n");
        else        asm volatile("cp.async.wait_group 0;\n");
        __syncthreads();
        if (it + 2 < 8) issue_chunk((it + 2) % 3, it + 2);

        const int st = it % 3;
#pragma unroll
        for (int ks = 0; ks < 2; ks++) {
            const int kk = ks * 16;
            u32 ahi[2][4], alo[2][4];
#pragma unroll
            for (int i = 0; i < 2; i++) {
                const int mb = wm + i * 16;
                ldsm_x4_t(ahi[i][0], ahi[i][1], ahi[i][2], ahi[i][3],
                          SA_(st, 0, kk + a_koff, mb + a_moff));
                ldsm_x4_t(alo[i][0], alo[i][1], alo[i][2], alo[i][3],
                          SA_(st, 1, kk + a_koff, mb + a_moff));
            }
            u32 bhi[4][2];
#pragma unroll
            for (int np = 0; np < 2; np++) {
                const int nb2 = wn + np * 16;
                u32 r0, r1, r2, r3;
                ldsm_x4_t(r0, r1, r2, r3, SW_(st, kk + b_koff, nb2 + b_noff));
                bhi[2 * np][0] = r0; bhi[2 * np][1] = r1;
                bhi[2 * np + 1][0] = r2; bhi[2 * np + 1][1] = r3;
            }
#pragma unroll
            for (int i = 0; i < 2; i++)
#pragma unroll
                for (int j = 0; j < 4; j++) {
                    mma_f16(acc[i][j], ahi[i], bhi[j][0], bhi[j][1]);
                    mma_f16(acc[i][j], alo[i], bhi[j][0], bhi[j][1]);
                }
        }
    }

    const int g = lane >> 2, tg = lane & 3;
    const int b = blockIdx.z;
#pragma unroll
    for (int i = 0; i < 2; i++)
#pragma unroll
        for (int j = 0; j < 4; j++) {
            const int row = m0 + wm + i * 16 + g;
            const int col = n0 + wn + j * 8 + 2 * tg;
            u32 h0, l0, h1, l1;
            bf16_split2(acc[i][j][0], acc[i][j][1], h0, l0);
            bf16_split2(acc[i][j][2], acc[i][j][3], h1, l1);
            if (col < 128) {
                const long k0i = ((long)(b * MPOOL) + row) * 128 + col;
                const long k1i = ((long)(b * MPOOL) + row + 8) * 128 + col;
                *(u32*)&g_kvhi[k0i] = h0;
                *(u32*)&g_kvlo[k0i] = l0;
                *(u32*)&g_kvhi[k1i] = h1;
                *(u32*)&g_kvlo[k1i] = l1;
            } else {
                const long vb = ((long)(b * 128 + (col - 128))) * MPOOL;
                ((u16*)g_vthi)[vb + row]              = (u16)(h0 & 0xffff);
                ((u16*)g_vthi)[vb + MPOOL + row]      = (u16)(h0 >> 16);
                ((u16*)g_vtlo)[vb + row]              = (u16)(l0 & 0xffff);
                ((u16*)g_vtlo)[vb + MPOOL + row]      = (u16)(l0 >> 16);
                ((u16*)g_vthi)[vb + row + 8]          = (u16)(h1 & 0xffff);
                ((u16*)g_vthi)[vb + MPOOL + row + 8]  = (u16)(h1 >> 16);
                ((u16*)g_vtlo)[vb + row + 8]          = (u16)(l1 & 0xffff);
                ((u16*)g_vtlo)[vb + MPOOL + row + 8]  = (u16)(l1 >> 16);
            }
        }
#undef SA_
#undef SW_
}

// ---------------------------------------------------------------------------
// 3-stage pipelined fp16x2 projection GEMM, K=128, A row-major fp16 hi/lo.
// out[(b*256+coff+n)*4096+m] = bias[n] + A@Wh.
// Smem/stage: A 2x128x40 + W 32x72 fp16 = 25088 B; 3 stages = 75264 B.
// ---------------------------------------------------------------------------
#define PJ_SMEM 75264
__global__ __launch_bounds__(256, 2) void gemm_proj_pipe(
    const __nv_bfloat16* __restrict__ Ahi, const __nv_bfloat16* __restrict__ Alo,
    long aBatch, int woff,
    const float* __restrict__ bias,
    float* __restrict__ out, int coff)
{
    extern __shared__ char smraw[];
    const u32 sbase = s2u(smraw);
#define SA_(st,hl,m,k) (sbase + (st)*25088 + ((((hl)*128)+(m))*40 + (k))*2)
#define SW_(st,k,n)    (sbase + (st)*25088 + 20480 + ((k)*72 + (n))*2)

    const int tid = threadIdx.x;
    const int wid = tid >> 5;
    const int lane = tid & 31;
    const int m0 = blockIdx.x * 128;
    const int n0 = blockIdx.y * 64;
    const int wm = (wid & 3) * 32;
    const int wn = (wid >> 2) * 32;
    const __nv_bfloat16* Ah = Ahi + (long)blockIdx.z * aBatch + (long)m0 * 128;
    const __nv_bfloat16* Al = Alo + (long)blockIdx.z * aBatch + (long)m0 * 128;
    const __nv_bfloat16* Wh = g_whi + woff + n0;

    const int l7 = lane & 7;
    const int a_moff = l7 + ((lane & 8) ? 8 : 0);
    const int a_koff = (lane & 16) ? 8 : 0;
    const int b_koff = l7 + ((lane & 8) ? 8 : 0);
    const int b_noff = (lane & 16) ? 8 : 0;

    const int ar0 = tid >> 2,          ac0 = (tid & 3) * 8;
    const int ar1 = (tid + 256) >> 2,  ac1 = ((tid + 256) & 3) * 8;
    const int wr = tid >> 3,           wc = (tid & 7) * 8;

    auto issue_chunk = [&](int st, int chunk) {
        const long kb = (long)chunk * 32;
        cp_cg(SA_(st, 0, ar0, ac0), Ah + (long)ar0 * 128 + kb + ac0);
        cp_cg(SA_(st, 1, ar0, ac0), Al + (long)ar0 * 128 + kb + ac0);
        cp_cg(SA_(st, 0, ar1, ac1), Ah + (long)ar1 * 128 + kb + ac1);
        cp_cg(SA_(st, 1, ar1, ac1), Al + (long)ar1 * 128 + kb + ac1);
        cp_cg(SW_(st, wr, wc), Wh + (kb + wr) * 128 + wc);
        CP_COMMIT();
    };

    float acc[2][4][4];
#pragma unroll
    for (int i = 0; i < 2; i++)
#pragma unroll
        for (int j = 0; j < 4; j++)
#pragma unroll
            for (int c = 0; c < 4; c++) acc[i][j][c] = 0.f;

    issue_chunk(0, 0);
    issue_chunk(1, 1);

#pragma unroll
    for (int it = 0; it < 4; it++) {
        if (it < 3) asm volatile("cp.async.wait_group 1;\n");
        else        asm volatile("cp.async.wait_group 0;\n");
        __syncthreads();
        if (it + 2 < 4) issue_chunk((it + 2) % 3, it + 2);

        const int st = it % 3;
#pragma unroll
        for (int ks = 0; ks < 2; ks++) {
            const int kk = ks * 16;
            u32 ahi[2][4], alo[2][4];
#pragma unroll
            for (int i = 0; i < 2; i++) {
                const int mb = wm + i * 16;
                ldsm_x4(ahi[i][0], ahi[i][1], ahi[i][2], ahi[i][3],
                        SA_(st, 0, mb + a_moff, kk + a_koff));
                ldsm_x4(alo[i][0], alo[i][1], alo[i][2], alo[i][3],
                        SA_(st, 1, mb + a_moff, kk + a_koff));
            }
            u32 bhi[4][2];
#pragma unroll
            for (int np = 0; np < 2; np++) {
                const int nb2 = wn + np * 16;
                u32 r0, r1, r2, r3;
                ldsm_x4_t(r0, r1, r2, r3, SW_(st, kk + b_koff, nb2 + b_noff));
                bhi[2 * np][0] = r0; bhi[2 * np][1] = r1;
                bhi[2 * np + 1][0] = r2; bhi[2 * np + 1][1] = r3;
            }
#pragma unroll
            for (int i = 0; i < 2; i++)
#pragma unroll
                for (int j = 0; j < 4; j++) {
                    mma_f16(acc[i][j], ahi[i], bhi[j][0], bhi[j][1]);
                    mma_f16(acc[i][j], alo[i], bhi[j][0], bhi[j][1]);
                }
        }
    }

    const int g = lane >> 2, tg = lane & 3;
    float* ob = out + ((long)blockIdx.z * 256 + coff) * 4096;
#pragma unroll
    for (int j = 0; j < 4; j++) {
        const int nl = n0 + wn + j * 8 + 2 * tg;
        const float bv0 = bias[nl];
        const float bv1 = bias[nl + 1];
#pragma unroll
        for (int i = 0; i < 2; i++) {
            const int m = m0 + wm + i * 16 + g;
            ob[(long)nl * 4096 + m]           = acc[i][j][0] + bv0;
            ob[(long)(nl + 1) * 4096 + m]     = acc[i][j][1] + bv1;
            ob[(long)nl * 4096 + m + 8]       = acc[i][j][2] + bv0;
            ob[(long)(nl + 1) * 4096 + m + 8] = acc[i][j][3] + bv1;
        }
    }
#undef SA_
#undef SW_
}

// ---------------------------------------------------------------------------
// hifi window attention: one warp per (b, window, head); emits fp16 hi/lo.
// ---------------------------------------------------------------------------
__global__ __launch_bounds__(256) void hifi_attn()
{
    const int wid = (blockIdx.x * blockDim.x + threadIdx.x) >> 5;
    const int lane = threadIdx.x & 31;
    const int head = wid & 3;
    const int win = (wid >> 2) & 1023;
    const int b = wid >> 12;
    const int hg = win >> 5, wgc = win & 31;

    float q[4], k[4], v[4];
    int t[4];
#pragma unroll
    for (int i = 0; i < 4; i++) {
        const int r = 2 * hg + (i >> 1);
        const int c = 2 * wgc + (i & 1);
        t[i] = r * 64 + c;
        const float* base = g_qkv + (long)(b * NTOK + t[i]) * 384 + head * 32 + lane;
        q[i] = base[0];
        k[i] = base[128];
        v[i] = base[256];
    }
    float s[4][4];
#pragma unroll
    for (int i = 0; i < 4; i++)
#pragma unroll
        for (int j = 0; j < 4; j++) {
            float p = q[i] * k[j];
#pragma unroll
            for (int off = 16; off; off >>= 1)
                p += __shfl_xor_sync(0xffffffffu, p, off);
            s[i][j] = p * ATTN_SCALE;
        }
#pragma unroll
    for (int i = 0; i < 4; i++) {
        float mx = fmaxf(fmaxf(s[i][0], s[i][1]), fmaxf(s[i][2], s[i][3]));
        float e0 = __expf(s[i][0] - mx);
        float e1 = __expf(s[i][1] - mx);
        float e2 = __expf(s[i][2] - mx);
        float e3 = __expf(s[i][3] - mx);
        float inv = 1.0f / (e0 + e1 + e2 + e3);
        float o = (e0 * v[0] + e1 * v[1] + e2 * v[2] + e3 * v[3]) * inv;
        const long idx = (long)(b * NTOK + t[i]) * 128 + head * 32 + lane;
        __half h = __float2half_rn(o);
        ((u16*)g_ohhi)[idx] = __half_as_ushort(h);
        ((u16*)g_ohlo)[idx] = __half_as_ushort(__float2half_rn(o - __half2float(h)));
    }
}

// ---------------------------------------------------------------------------
// lofi flash attention (bf16x3 internals, m16n8k16), KV pre-split bf16 hi/lo:
// staging is pure double-buffered cp.async. Emits fp16 hi/lo outputs.
// Smem per stage: Khi 64x40 + Klo 64x40 + Vhi 32x72 + Vlo 32x72 bf16 = 19456 B.
// ---------------------------------------------------------------------------
#define LST 19456
#define LKH 0
#define LKL 5120
#define LVH 10240
#define LVL 14848
__global__ __launch_bounds__(256, 2) void lofi_attn_mma()
{
    __shared__ __align__(16) char smv[2][LST];

    const int tid = threadIdx.x;
    const int lane = tid & 31;
    const int warp = tid >> 5;
    const int g = lane >> 2;
    const int tg = lane & 3;
    const int bh = blockIdx.y;
    const int b = bh >> 2, head = bh & 3;
    const int qrow0 = blockIdx.x * 128 + warp * 16;

    const __nv_bfloat16* kh = g_kvhi + (long)(b * MPOOL) * 128 + head * 32;
    const __nv_bfloat16* kl = g_kvlo + (long)(b * MPOOL) * 128 + head * 32;
    const __nv_bfloat16* vh = g_vthi + (long)(b * 128 + head * 32) * MPOOL;
    const __nv_bfloat16* vl = g_vtlo + (long)(b * 128 + head * 32) * MPOOL;

    auto fill = [&](int st, int j0) {
        const u32 base = s2u(smv[st]);
        {   // K: 64 rows x 32 dims, hi + lo
            const int r = tid >> 2, gc = tid & 3;
            cp_cg(base + LKH + r * 80 + gc * 16, kh + (long)(j0 + r) * 128 + gc * 8);
            cp_cg(base + LKL + r * 80 + gc * 16, kl + (long)(j0 + r) * 128 + gc * 8);
        }
        {   // V^T: 32 d-rows x 64 kv, hi + lo
            const int r = tid >> 3, gc = tid & 7;
            cp_cg(base + LVH + r * 144 + gc * 16, vh + (long)r * MPOOL + j0 + gc * 8);
            cp_cg(base + LVL + r * 144 + gc * 16, vl + (long)r * MPOOL + j0 + gc * 8);
        }
        CP_COMMIT();
    };

    // Q fragments (loop-invariant), pre-scaled, bf16 hi/lo split
    const float* qbase = g_ql + ((long)(b * NTOK + qrow0)) * 128 + head * 32;
    u32 qa_hi[2][4], qa_lo[2][4];
#pragma unroll
    for (int kt = 0; kt < 2; kt++) {
        float2 f0 = *(const float2*)&qbase[(long)g * 128 + kt * 16 + 2 * tg];
        float2 f1 = *(const float2*)&qbase[(long)(g + 8) * 128 + kt * 16 + 2 * tg];
        float2 f2 = *(const float2*)&qbase[(long)g * 128 + kt * 16 + 8 + 2 * tg];
        float2 f3 = *(const float2*)&qbase[(long)(g + 8) * 128 + kt * 16 + 8 + 2 * tg];
        bf16_split2(f0.x * ATTN_SCALE, f0.y * ATTN_SCALE, qa_hi[kt][0], qa_lo[kt][0]);
        bf16_split2(f1.x * ATTN_SCALE, f1.y * ATTN_SCALE, qa_hi[kt][1], qa_lo[kt][1]);
        bf16_split2(f2.x * ATTN_SCALE, f2.y * ATTN_SCALE, qa_hi[kt][2], qa_lo[kt][2]);
        bf16_split2(f3.x * ATTN_SCALE, f3.y * ATTN_SCALE, qa_hi[kt][3], qa_lo[kt][3]);
    }

    float od[4][4];
#pragma unroll
    for (int dt = 0; dt < 4; dt++)
#pragma unroll
        for (int c = 0; c < 4; c++) od[dt][c] = 0.f;
    float mrow[2] = {-1e30f, -1e30f};
    float lrow[2] = {0.f, 0.f};

    fill(0, 0);

    for (int c = 0; c < 16; c++) {
        if (c + 1 < 16) {
            fill((c + 1) & 1, (c + 1) * 64);
            asm volatile("cp.async.wait_group 1;\n");
        } else {
            asm volatile("cp.async.wait_group 0;\n");
        }
        __syncthreads();

        const char* sb = smv[c & 1];
        const char* sKhiB = sb + LKH;
        const char* sKloB = sb + LKL;
        const char* sVhiB = sb + LVH;
        const char* sVloB = sb + LVL;

        // --- QK^T: 8 n-tiles of 8 kv cols, bf16x3 ---
        float s[8][4];
#pragma unroll
        for (int nt = 0; nt < 8; nt++) {
            float cc[4] = {0.f, 0.f, 0.f, 0.f};
            const int kv = nt * 8 + g;
#pragma unroll
            for (int kt = 0; kt < 2; kt++) {
                const int kk = kt * 16;
                u32 bh0 = *(const u32*)(sKhiB + kv * 80 + (kk + 2 * tg) * 2);
                u32 bh1 = *(const u32*)(sKhiB + kv * 80 + (kk + 8 + 2 * tg) * 2);
                u32 bl0 = *(const u32*)(sKloB + kv * 80 + (kk + 2 * tg) * 2);
                u32 bl1 = *(const u32*)(sKloB + kv * 80 + (kk + 8 + 2 * tg) * 2);
                mma_bf16(cc, qa_hi[kt], bh0, bh1);
                mma_bf16(cc, qa_lo[kt], bh0, bh1);
                mma_bf16(cc, qa_hi[kt], bl0, bl1);
            }
            s[nt][0] = cc[0]; s[nt][1] = cc[1]; s[nt][2] = cc[2]; s[nt][3] = cc[3];
        }

        // --- online softmax (rows g and g+8) ---
        float mx0 = s[0][0], mx1 = s[0][2];
#pragma unroll
        for (int nt = 0; nt < 8; nt++) {
            mx0 = fmaxf(mx0, fmaxf(s[nt][0], s[nt][1]));
            mx1 = fmaxf(mx1, fmaxf(s[nt][2], s[nt][3]));
        }
        mx0 = fmaxf(mx0, __shfl_xor_sync(0xffffffffu, mx0, 1));
        mx0 = fmaxf(mx0, __shfl_xor_sync(0xffffffffu, mx0, 2));
        mx1 = fmaxf(mx1, __shfl_xor_sync(0xffffffffu, mx1, 1));
        mx1 = fmaxf(mx1, __shfl_xor_sync(0xffffffffu, mx1, 2));

        const float mn0 = fmaxf(mrow[0], mx0);
        const float mn1 = fmaxf(mrow[1], mx1);
        const float sf0 = __expf(mrow[0] - mn0);
        const float sf1 = __expf(mrow[1] - mn1);
        mrow[0] = mn0; mrow[1] = mn1;
        lrow[0] *= sf0; lrow[1] *= sf1;
#pragma unroll
        for (int dt = 0; dt < 4; dt++) {
            od[dt][0] *= sf0; od[dt][1] *= sf0;
            od[dt][2] *= sf1; od[dt][3] *= sf1;
        }
#pragma unroll
        for (int nt = 0; nt < 8; nt++) {
            s[nt][0] = __expf(s[nt][0] - mn0);
            s[nt][1] = __expf(s[nt][1] - mn0);
            s[nt][2] = __expf(s[nt][2] - mn1);
            s[nt][3] = __expf(s[nt][3] - mn1);
            lrow[0] += s[nt][0] + s[nt][1];
            lrow[1] += s[nt][2] + s[nt][3];
        }

        // --- PV: 4 k-tiles of 16 kv, 4 d-tiles of 8, bf16x3 ---
#pragma unroll
        for (int kt2 = 0; kt2 < 4; kt2++) {
            u32 pa_hi[4], pa_lo[4];
            bf16_split2(s[2 * kt2][0],     s[2 * kt2][1],     pa_hi[0], pa_lo[0]);
            bf16_split2(s[2 * kt2][2],     s[2 * kt2][3],     pa_hi[1], pa_lo[1]);
            bf16_split2(s[2 * kt2 + 1][0], s[2 * kt2 + 1][1], pa_hi[2], pa_lo[2]);
            bf16_split2(s[2 * kt2 + 1][2], s[2 * kt2 + 1][3], pa_hi[3], pa_lo[3]);
            const int kv0 = kt2 * 16;
#pragma unroll
            for (int dt = 0; dt < 4; dt++) {
                const int d = dt * 8 + g;
                u32 vb_h0 = *(const u32*)(sVhiB + d * 144 + (kv0 + 2 * tg) * 2);
                u32 vb_h1 = *(const u32*)(sVhiB + d * 144 + (kv0 + 8 + 2 * tg) * 2);
                u32 vb_l0 = *(const u32*)(sVloB + d * 144 + (kv0 + 2 * tg) * 2);
                u32 vb_l1 = *(const u32*)(sVloB + d * 144 + (kv0 + 8 + 2 * tg) * 2);
                mma_bf16(od[dt], pa_hi, vb_h0, vb_h1);
                mma_bf16(od[dt], pa_lo, vb_h0, vb_h1);
                mma_bf16(od[dt], pa_hi, vb_l0, vb_l1);
            }
        }
        __syncthreads();
    }

    lrow[0] += __shfl_xor_sync(0xffffffffu, lrow[0], 1);
    lrow[0] += __shfl_xor_sync(0xffffffffu, lrow[0], 2);
    lrow[1] += __shfl_xor_sync(0xffffffffu, lrow[1], 1);
    lrow[1] += __shfl_xor_sync(0xffffffffu, lrow[1], 2);
    const float inv0 = 1.0f / lrow[0];
    const float inv1 = 1.0f / lrow[1];

    const long obase = ((long)(b * NTOK + qrow0)) * 128 + head * 32;
#pragma unroll
    for (int dt = 0; dt < 4; dt++) {
        const int col = dt * 8 + 2 * tg;
        u32 h, l;
        f16_split2(od[dt][0] * inv0, od[dt][1] * inv0, h, l);
        *(u32*)&g_olhi[obase + (long)g * 128 + col] = h;
        *(u32*)&g_ollo[obase + (long)g * 128 + col] = l;
        f16_split2(od[dt][2] * inv1, od[dt][3] * inv1, h, l);
        *(u32*)&g_olhi[obase + (long)(g + 8) * 128 + col] = h;
        *(u32*)&g_ollo[obase + (long)(g + 8) * 128 + col] = l;
    }
}

// ---------------------------------------------------------------------------
extern "C" void kernel_launch(void* const* d_in, const int* in_sizes, int n_in,
                              void* d_out, int out_size)
{
    const float* x        = (const float*)d_in[0];
    const float* l_q_w    = (const float*)d_in[1];
    const float* l_kv_w   = (const float*)d_in[2];
    const float* l_proj_w = (const float*)d_in[3];
    const float* l_proj_b = (const float*)d_in[4];
    const float* h_qkv_w  = (const float*)d_in[5];
    const float* h_proj_w = (const float*)d_in[6];
    const float* h_proj_b = (const float*)d_in[7];
    float* out = (float*)d_out;

    cudaFuncSetAttribute(gemm_xt_pipe,
                         cudaFuncAttributeMaxDynamicSharedMemorySize, XT_SMEM);
    cudaFuncSetAttribute(gemm_kv_pipe,
                         cudaFuncAttributeMaxDynamicSharedMemorySize, XT_SMEM);
    cudaFuncSetAttribute(gemm_proj_pipe,
                         cudaFuncAttributeMaxDynamicSharedMemorySize, PJ_SMEM);

    float *qkv, *ql;
    __nv_bfloat16 *xhi, *xlo, *phi, *plo, *ohhi, *ohlo, *olhi, *ollo;
    cudaGetSymbolAddress((void**)&qkv,  g_qkv);
    cudaGetSymbolAddress((void**)&ql,   g_ql);
    cudaGetSymbolAddress((void**)&xhi,  g_xhi);
    cudaGetSymbolAddress((void**)&xlo,  g_xlo);
    cudaGetSymbolAddress((void**)&phi,  g_phi);
    cudaGetSymbolAddress((void**)&plo,  g_plo);
    cudaGetSymbolAddress((void**)&ohhi, g_ohhi);
    cudaGetSymbolAddress((void**)&ohlo, g_ohlo);
    cudaGetSymbolAddress((void**)&olhi, g_olhi);
    cudaGetSymbolAddress((void**)&ollo, g_ollo);

    // operand conversion
    convert_w<<<224, 256>>>(h_qkv_w, l_q_w, l_kv_w, h_proj_w, l_proj_w);
    convert_x_pool<<<BB * CDIM, 256>>>(x);

    // hifi qkv: x^T @ h_qkv_w -> [b][4096][384] fp32
    gemm_xt_pipe<<<dim3(32, 6, 8), 256, XT_SMEM>>>(
        xhi, xlo, (long)CDIM * NTOK, WOFF_HQKV, qkv, (long)NTOK * 384, NTOK, 384);
    // lofi q: x^T @ l_q_w -> [b][4096][128] fp32
    gemm_xt_pipe<<<dim3(32, 2, 8), 256, XT_SMEM>>>(
        xhi, xlo, (long)CDIM * NTOK, WOFF_LQ, ql, (long)NTOK * 128, NTOK, 128);
    // lofi kv: pooled^T @ l_kv_w -> bf16 hi/lo (K direct, V transposed)
    gemm_kv_pipe<<<dim3(8, 4, 8), 256, XT_SMEM>>>(phi, plo, (long)CDIM * MPOOL);

    // attention (emit fp16 hi/lo)
    hifi_attn<<<4096, 256>>>();
    lofi_attn_mma<<<dim3(32, 32), 256>>>();

    // projections, fused concat+transpose into output
    gemm_proj_pipe<<<dim3(32, 2, 8), 256, PJ_SMEM>>>(
        ohhi, ohlo, (long)NTOK * 128, WOFF_HPROJ, h_proj_b, out, 0);
    gemm_proj_pipe<<<dim3(32, 2, 8), 256, PJ_SMEM>>>(
        olhi, ollo, (long)NTOK * 128, WOFF_LPROJ, l_proj_b, out, 128);
}